// round 1
// baseline (speedup 1.0000x reference)
#include <cuda_runtime.h>
#include <math.h>

// ---------------- problem constants ----------------
#define B_   2
#define K_   384
#define N_   4096
#define D_   1024
#define H_   150
#define HP_  152      // padded H (zero pad) for float4
#define L_   12
#define NB_  10
#define DE_  20

#define SZ_U   (B_*K_*D_)       // 786432
#define SZ_LR  (B_*K_*HP_)      // 116736
#define SZ_DP  (NB_*HP_)        // 1520
#define SZ_P   (B_*K_*K_)       // 294912
#define SZ_S   (B_*K_)          // 768

// ---------------- device scratch (static, no allocs) ----------------
__device__ float g_u[SZ_U];
__device__ float g_l[SZ_LR];
__device__ float g_r[SZ_LR];
__device__ float g_dp[SZ_DP];
__device__ float g_probs[SZ_P];
__device__ float g_probsT[SZ_P];
__device__ float g_invrow[SZ_S];
__device__ float g_invcol[SZ_S];
__device__ float g_c1[SZ_U];
__device__ float g_c2[SZ_U];
__device__ float g_tmp[SZ_U];
__device__ float g_ctxt[SZ_U];
__device__ float g_gate[SZ_U];

// ---------------- init: dist-proj table + l/r pad zeroing ----------------
__global__ void init_misc_kernel(const float* __restrict__ dist_emb,
                                 const float* __restrict__ Wd,
                                 const float* __restrict__ bd,
                                 float* __restrict__ dp,
                                 float* __restrict__ l,
                                 float* __restrict__ r)
{
    int tid = threadIdx.x;
    // dp[n][h] = dist_emb[n,:] @ Wd[:,h] + bd[h]   (zero in pad cols)
    for (int idx = tid; idx < SZ_DP; idx += blockDim.x) {
        int n = idx / HP_, h = idx % HP_;
        float v = 0.f;
        if (h < H_) {
            v = bd[h];
            #pragma unroll
            for (int t = 0; t < DE_; t++)
                v += dist_emb[n * DE_ + t] * Wd[t * H_ + h];
        }
        dp[idx] = v;
    }
    // zero pad columns of l and r (cols 150,151) for all B*K rows
    for (int idx = tid; idx < B_ * K_ * 2; idx += blockDim.x) {
        int row = idx >> 1, c = H_ + (idx & 1);
        l[row * HP_ + c] = 0.f;
        r[row * HP_ + c] = 0.f;
    }
}

// ---------------- generic tiled SGEMM ----------------
// C[z] = act( rowscale * ( beta*C + A[z] @ W[z] + bias ) )
// A: [M,K] lda=K.  W: [K,N] ldw=N.  C: ldc given.
// act: 0=none, 1=tanh, 2=sigmoid
__global__ void sgemm_kernel(const float* __restrict__ A,
                             const float* __restrict__ W,
                             const float* __restrict__ bias,
                             const float* __restrict__ rowscale,
                             float* __restrict__ C,
                             int M, int N, int K, int ldc,
                             long sA, long sW, long sC, int sRS,
                             int beta, int act)
{
    __shared__ float As[16][68];
    __shared__ float Ws[16][68];

    int z = blockIdx.z;
    A += (long)z * sA;
    W += (long)z * sW;
    C += (long)z * sC;
    if (rowscale) rowscale += (long)z * sRS;

    int m0 = blockIdx.y * 64, n0 = blockIdx.x * 64;
    int tid = threadIdx.x;
    int tx = tid & 15, ty = tid >> 4;

    float acc[4][4];
    #pragma unroll
    for (int i = 0; i < 4; i++)
        #pragma unroll
        for (int j = 0; j < 4; j++) acc[i][j] = 0.f;

    for (int k0 = 0; k0 < K; k0 += 16) {
        // A tile: 64 rows x 16 k, one float4 per thread (along k)
        {
            int rr = tid >> 2, q = tid & 3;
            int grow = m0 + rr;
            float4 v = make_float4(0.f, 0.f, 0.f, 0.f);
            if (grow < M)
                v = *(const float4*)(A + (long)grow * K + k0 + q * 4);
            As[q * 4 + 0][rr] = v.x;
            As[q * 4 + 1][rr] = v.y;
            As[q * 4 + 2][rr] = v.z;
            As[q * 4 + 3][rr] = v.w;
        }
        // W tile: 16 k x 64 n, scalar coalesced
        #pragma unroll
        for (int t = 0; t < 4; t++) {
            int idx = tid + t * 256;
            int kk = idx >> 6, n = idx & 63;
            int gn = n0 + n;
            Ws[kk][n] = (gn < N) ? W[(long)(k0 + kk) * N + gn] : 0.f;
        }
        __syncthreads();
        #pragma unroll
        for (int kk = 0; kk < 16; kk++) {
            float4 a4 = *(const float4*)&As[kk][ty * 4];
            float4 b4 = *(const float4*)&Ws[kk][tx * 4];
            acc[0][0] += a4.x * b4.x; acc[0][1] += a4.x * b4.y;
            acc[0][2] += a4.x * b4.z; acc[0][3] += a4.x * b4.w;
            acc[1][0] += a4.y * b4.x; acc[1][1] += a4.y * b4.y;
            acc[1][2] += a4.y * b4.z; acc[1][3] += a4.y * b4.w;
            acc[2][0] += a4.z * b4.x; acc[2][1] += a4.z * b4.y;
            acc[2][2] += a4.z * b4.z; acc[2][3] += a4.z * b4.w;
            acc[3][0] += a4.w * b4.x; acc[3][1] += a4.w * b4.y;
            acc[3][2] += a4.w * b4.z; acc[3][3] += a4.w * b4.w;
        }
        __syncthreads();
    }

    int mbase = m0 + ty * 4, nbase = n0 + tx * 4;
    #pragma unroll
    for (int i = 0; i < 4; i++) {
        int gm = mbase + i;
        if (gm >= M) continue;
        float rs = rowscale ? rowscale[gm] : 1.f;
        #pragma unroll
        for (int j = 0; j < 4; j++) {
            int gn = nbase + j;
            if (gn >= N) continue;
            float v = acc[i][j];
            long off = (long)gm * ldc + gn;
            if (beta) v += C[off];
            if (bias) v += bias[gn];
            v *= rs;
            if (act == 1) v = tanhf(v);
            else if (act == 2) v = 1.f / (1.f + expf(-v));
            C[off] = v;
        }
    }
}

// ---------------- fused pairwise scorer ----------------
// scores[b,i,j,:] (+)= relu(l_i + r_j + dp[bucket(begin_j - end_i)]) @ Wo + bo
__global__ void scorer_kernel(const float* __restrict__ l,
                              const float* __restrict__ r,
                              const float* __restrict__ dp,
                              const float* __restrict__ Wo,
                              const float* __restrict__ bo,
                              const int* __restrict__ span_begin,
                              const int* __restrict__ span_end,
                              float* __restrict__ scores,
                              int first)
{
    int i = blockIdx.x, b = blockIdx.y;
    int tid = threadIdx.x;

    __shared__ float s_l[HP_];
    __shared__ float s_dp[NB_][HP_];
    __shared__ float s_wot[L_][HP_];
    __shared__ float s_bo[L_];

    for (int idx = tid; idx < HP_; idx += blockDim.x)
        s_l[idx] = l[(b * K_ + i) * HP_ + idx];
    for (int idx = tid; idx < NB_ * HP_; idx += blockDim.x)
        s_dp[idx / HP_][idx % HP_] = dp[idx];
    for (int idx = tid; idx < L_ * HP_; idx += blockDim.x) {
        int c = idx / HP_, h = idx % HP_;
        s_wot[c][h] = (h < H_) ? Wo[h * L_ + c] : 0.f;
    }
    if (tid < L_) s_bo[tid] = bo[tid];
    __syncthreads();

    int endi = span_end[b * K_ + i];
    const float* rb = r + (long)b * K_ * HP_;

    for (int j = tid; j < K_; j += blockDim.x) {
        int d = span_begin[b * K_ + j] - endi;
        int da = d < 0 ? -d : d;
        int bk;
        if (da <= 4) bk = da;
        else {
            int lg = 31 - __clz(da) + 3;
            bk = lg < (NB_ - 1) ? lg : (NB_ - 1);
        }
        const float* rj = rb + j * HP_;
        const float* dpk = s_dp[bk];

        float acc[L_];
        #pragma unroll
        for (int c = 0; c < L_; c++) acc[c] = s_bo[c];

        #pragma unroll 4
        for (int h = 0; h < HP_; h += 4) {
            float4 rv = *(const float4*)(rj + h);
            float4 lv = *(const float4*)(s_l + h);
            float4 dv = *(const float4*)(dpk + h);
            float h0 = fmaxf(lv.x + rv.x + dv.x, 0.f);
            float h1 = fmaxf(lv.y + rv.y + dv.y, 0.f);
            float h2 = fmaxf(lv.z + rv.z + dv.z, 0.f);
            float h3 = fmaxf(lv.w + rv.w + dv.w, 0.f);
            #pragma unroll
            for (int c = 0; c < L_; c++) {
                float4 w = *(const float4*)(&s_wot[c][h]);
                acc[c] += h0 * w.x + h1 * w.y + h2 * w.z + h3 * w.w;
            }
        }

        float* out = scores + (((long)(b * K_ + i)) * K_ + j) * L_;
        if (first) {
            #pragma unroll
            for (int q = 0; q < 3; q++)
                *(float4*)(out + q * 4) = make_float4(acc[q*4], acc[q*4+1], acc[q*4+2], acc[q*4+3]);
        } else {
            #pragma unroll
            for (int q = 0; q < 3; q++) {
                float4 old = *(const float4*)(out + q * 4);
                *(float4*)(out + q * 4) = make_float4(old.x + acc[q*4], old.y + acc[q*4+1],
                                                      old.z + acc[q*4+2], old.w + acc[q*4+3]);
            }
        }
    }
}

// ---------------- probs = sigmoid(max_l scores) * mask ; also transpose ----------------
__global__ void probs_kernel(const float* __restrict__ scores,
                             const float* __restrict__ mask,
                             float* __restrict__ probs,
                             float* __restrict__ probsT)
{
    int i = blockIdx.x, b = blockIdx.y;
    for (int j = threadIdx.x; j < K_; j += blockDim.x) {
        const float* s = scores + (((long)(b * K_ + i)) * K_ + j) * L_;
        float m = s[0];
        #pragma unroll
        for (int c = 1; c < L_; c++) m = fmaxf(m, s[c]);
        float p = (1.f / (1.f + expf(-m))) * mask[((long)(b * K_ + i)) * K_ + j];
        probs[((long)(b * K_ + i)) * K_ + j] = p;
        probsT[((long)(b * K_ + j)) * K_ + i] = p;
    }
}

// ---------------- inverse row sums ----------------
__global__ void invsum_kernel(const float* __restrict__ probs,
                              const float* __restrict__ probsT,
                              float* __restrict__ invrow,
                              float* __restrict__ invcol)
{
    int row = blockIdx.x;
    const float* src;
    float* dst;
    if (row < B_ * K_) { src = probs + (long)row * K_;  dst = invrow + row; }
    else               { src = probsT + (long)(row - B_ * K_) * K_; dst = invcol + row - B_ * K_; }
    float s = 0.f;
    for (int j = threadIdx.x; j < K_; j += blockDim.x) s += src[j];
    __shared__ float red[4];
    #pragma unroll
    for (int o = 16; o > 0; o >>= 1) s += __shfl_down_sync(0xffffffffu, s, o);
    int wid = threadIdx.x >> 5;
    if ((threadIdx.x & 31) == 0) red[wid] = s;
    __syncthreads();
    if (threadIdx.x == 0) {
        s = red[0] + red[1] + red[2] + red[3];
        *dst = 1.f / (s + 1e-7f);
    }
}

// ---------------- gate: u = g*u + (1-g)*ctxt ----------------
__global__ void gate_kernel(const float* __restrict__ g,
                            const float* __restrict__ ctxt,
                            float* __restrict__ u)
{
    int i = blockIdx.x * blockDim.x + threadIdx.x;
    if (i < SZ_U) {
        float gg = g[i];
        u[i] = gg * u[i] + (1.f - gg) * ctxt[i];
    }
}

// ---------------- scatter with last-write-wins semantics ----------------
__global__ void scatter_kernel(const float* __restrict__ u,
                               const float* __restrict__ all_span,
                               const int* __restrict__ prune,
                               const int* __restrict__ span_len,
                               float* __restrict__ out_all)
{
    int bk = blockIdx.x;
    int b = bk / K_, k = bk % K_;
    int idx = prune[bk];
    bool last = (k == K_ - 1) || (prune[bk + 1] != idx);
    if (!last) return;
    bool valid = k < span_len[b];
    const float* src = valid ? (u + (long)bk * D_)
                             : (all_span + ((long)b * N_ + idx) * D_);
    float* dst = out_all + ((long)b * N_ + idx) * D_;
    int t = threadIdx.x;
    float4 v = *(const float4*)(src + t * 4);
    *(float4*)(dst + t * 4) = v;
}

// ---------------- host orchestration ----------------
extern "C" void kernel_launch(void* const* d_in, const int* in_sizes, int n_in,
                              void* d_out, int out_size)
{
    const float* span_vecs  = (const float*)d_in[0];
    const float* all_span   = (const float*)d_in[1];
    const int*   span_begin = (const int*)  d_in[2];
    const int*   span_end   = (const int*)  d_in[3];
    const float* mask       = (const float*)d_in[4];
    const int*   prune      = (const int*)  d_in[5];
    const int*   span_len   = (const int*)  d_in[6];
    const float* Wl  = (const float*)d_in[8];
    const float* bl  = (const float*)d_in[9];
    const float* Wr  = (const float*)d_in[10];
    const float* br  = (const float*)d_in[11];
    const float* de  = (const float*)d_in[12];
    const float* Wd  = (const float*)d_in[13];
    const float* bd  = (const float*)d_in[14];
    const float* Wo  = (const float*)d_in[15];
    const float* bo  = (const float*)d_in[16];
    const float* Wff1= (const float*)d_in[17];
    const float* Wff2= (const float*)d_in[18];
    const float* Wg  = (const float*)d_in[19];
    const float* bg  = (const float*)d_in[20];

    float *u, *l, *r, *dp, *probs, *probsT, *invrow, *invcol, *c1, *c2, *tmp, *ctxt, *gate;
    cudaGetSymbolAddress((void**)&u,      g_u);
    cudaGetSymbolAddress((void**)&l,      g_l);
    cudaGetSymbolAddress((void**)&r,      g_r);
    cudaGetSymbolAddress((void**)&dp,     g_dp);
    cudaGetSymbolAddress((void**)&probs,  g_probs);
    cudaGetSymbolAddress((void**)&probsT, g_probsT);
    cudaGetSymbolAddress((void**)&invrow, g_invrow);
    cudaGetSymbolAddress((void**)&invcol, g_invcol);
    cudaGetSymbolAddress((void**)&c1,     g_c1);
    cudaGetSymbolAddress((void**)&c2,     g_c2);
    cudaGetSymbolAddress((void**)&tmp,    g_tmp);
    cudaGetSymbolAddress((void**)&ctxt,   g_ctxt);
    cudaGetSymbolAddress((void**)&gate,   g_gate);

    float* out_all = (float*)d_out;
    float* out_u   = out_all + (size_t)B_ * N_ * D_;
    float* out_sc  = out_u   + (size_t)B_ * K_ * D_;

    const int M = B_ * K_;  // 768

    cudaMemcpyAsync(u, span_vecs, sizeof(float) * SZ_U, cudaMemcpyDeviceToDevice);
    init_misc_kernel<<<1, 256>>>(de, Wd, bd, dp, l, r);

    // initial projections + scorer
    sgemm_kernel<<<dim3(3, 12, 1), 256>>>(u, Wl, bl, nullptr, l, M, H_, D_, HP_, 0,0,0,0, 0, 0);
    sgemm_kernel<<<dim3(3, 12, 1), 256>>>(u, Wr, br, nullptr, r, M, H_, D_, HP_, 0,0,0,0, 0, 0);
    scorer_kernel<<<dim3(K_, B_), 128>>>(l, r, dp, Wo, bo, span_begin, span_end, out_sc, 1);

    for (int it = 0; it < 2; it++) {
        probs_kernel<<<dim3(K_, B_), 128>>>(out_sc, mask, probs, probsT);
        invsum_kernel<<<2 * B_ * K_, 128>>>(probs, probsT, invrow, invcol);

        // ctxt1 = (P @ u) * invrow ; ctxt2 = (P^T @ u) * invcol    (batched, grid.z = B)
        sgemm_kernel<<<dim3(16, 6, B_), 256>>>(probs,  u, nullptr, invrow, c1,
                                               K_, D_, K_, D_,
                                               (long)K_*K_, (long)K_*D_, (long)K_*D_, K_, 0, 0);
        sgemm_kernel<<<dim3(16, 6, B_), 256>>>(probsT, u, nullptr, invcol, c2,
                                               K_, D_, K_, D_,
                                               (long)K_*K_, (long)K_*D_, (long)K_*D_, K_, 0, 0);

        // tmp = tanh(u@Wff1a + c1@Wff1b + c2@Wff1c)
        sgemm_kernel<<<dim3(16, 12, 1), 256>>>(u,  Wff1,            nullptr, nullptr, tmp, M, D_, D_, D_, 0,0,0,0, 0, 0);
        sgemm_kernel<<<dim3(16, 12, 1), 256>>>(c1, Wff1 +   D_*D_,  nullptr, nullptr, tmp, M, D_, D_, D_, 0,0,0,0, 1, 0);
        sgemm_kernel<<<dim3(16, 12, 1), 256>>>(c2, Wff1 + 2*D_*D_,  nullptr, nullptr, tmp, M, D_, D_, D_, 0,0,0,0, 1, 1);
        // ctxt = tmp @ Wff2
        sgemm_kernel<<<dim3(16, 12, 1), 256>>>(tmp, Wff2,           nullptr, nullptr, ctxt, M, D_, D_, D_, 0,0,0,0, 0, 0);
        // g = sigmoid(u@Wg_a + ctxt@Wg_b + bg)
        sgemm_kernel<<<dim3(16, 12, 1), 256>>>(u,    Wg,            nullptr, nullptr, gate, M, D_, D_, D_, 0,0,0,0, 0, 0);
        sgemm_kernel<<<dim3(16, 12, 1), 256>>>(ctxt, Wg + D_*D_,    bg,      nullptr, gate, M, D_, D_, D_, 0,0,0,0, 1, 2);
        // u = g*u + (1-g)*ctxt
        gate_kernel<<<(SZ_U + 255) / 256, 256>>>(gate, ctxt, u);

        // re-project + scorer (residual accumulate)
        sgemm_kernel<<<dim3(3, 12, 1), 256>>>(u, Wl, bl, nullptr, l, M, H_, D_, HP_, 0,0,0,0, 0, 0);
        sgemm_kernel<<<dim3(3, 12, 1), 256>>>(u, Wr, br, nullptr, r, M, H_, D_, HP_, 0,0,0,0, 0, 0);
        scorer_kernel<<<dim3(K_, B_), 128>>>(l, r, dp, Wo, bo, span_begin, span_end, out_sc, 0);
    }

    // outputs: update_all, u, scores (scores already written in place)
    cudaMemcpyAsync(out_all, all_span, sizeof(float) * (size_t)B_ * N_ * D_, cudaMemcpyDeviceToDevice);
    scatter_kernel<<<B_ * K_, 256>>>(u, all_span, prune, span_len, out_all);
    cudaMemcpyAsync(out_u, u, sizeof(float) * SZ_U, cudaMemcpyDeviceToDevice);
}

// round 2
// speedup vs baseline: 1.3562x; 1.3562x over previous
#include <cuda_runtime.h>
#include <math.h>

// ---------------- problem constants ----------------
#define B_   2
#define K_   384
#define N_   4096
#define D_   1024
#define H_   150
#define HP_  152      // padded H
#define LRW_ 304      // l|r concatenated row width (2*HP_)
#define L_   12
#define NB_  10
#define DE_  20

#define SZ_U   (B_*K_*D_)       // 786432
#define SZ_P   (B_*K_*K_)       // 294912
#define SZ_S   (B_*K_)          // 768

// ---------------- device scratch (static, no allocs) ----------------
__device__ float g_u[SZ_U];
__device__ float g_u2[SZ_U];
__device__ float g_lr[B_*K_*LRW_];
__device__ float g_wlr[D_*LRW_];
__device__ float g_blr[LRW_];
__device__ float g_dp[NB_*HP_];
__device__ float g_probs[2*SZ_P];     // [probs b0, probs b1, probsT b0, probsT b1]
__device__ float g_inv[2*SZ_S];
__device__ float g_c[2*SZ_U];         // [c1 (b0,b1), c2 (b0,b1)]
__device__ float g_tmp[SZ_U];
__device__ float g_ctxt[SZ_U];

// ---------------- init: dp table + W_lr / b_lr concat ----------------
__global__ void init_kernel(const float* __restrict__ dist_emb,
                            const float* __restrict__ Wd,
                            const float* __restrict__ bd,
                            const float* __restrict__ Wl,
                            const float* __restrict__ bl,
                            const float* __restrict__ Wr,
                            const float* __restrict__ br,
                            float* __restrict__ dp,
                            float* __restrict__ wlr,
                            float* __restrict__ blr)
{
    int tid = blockIdx.x * blockDim.x + threadIdx.x;
    int nthr = gridDim.x * blockDim.x;
    // dp[n][h]
    for (int idx = tid; idx < NB_*HP_; idx += nthr) {
        int n = idx / HP_, h = idx % HP_;
        float v = 0.f;
        if (h < H_) {
            v = bd[h];
            #pragma unroll
            for (int t = 0; t < DE_; t++)
                v += dist_emb[n * DE_ + t] * Wd[t * H_ + h];
        }
        dp[idx] = v;
    }
    // wlr[k][c]: c<150 -> Wl, 152<=c<302 -> Wr, else 0
    for (int idx = tid; idx < D_*LRW_; idx += nthr) {
        int k = idx / LRW_, c = idx % LRW_;
        float v = 0.f;
        if (c < H_) v = Wl[k * H_ + c];
        else if (c >= HP_ && c < HP_ + H_) v = Wr[k * H_ + (c - HP_)];
        wlr[idx] = v;
    }
    for (int c = tid; c < LRW_; c += nthr) {
        float v = 0.f;
        if (c < H_) v = bl[c];
        else if (c >= HP_ && c < HP_ + H_) v = br[c - HP_];
        blr[c] = v;
    }
}

// ---------------- SGEMM: 64x64x16 tiles, 128 thr, 8x4 micro, double-buffered ----------------
// A segmented along K in 1024-wide chunks: seg0=a0, seg1=a1, seg2=a2 (lda each).
// C = act( rowscale * (A @ W + bias) )
// act: 0=none, 1=tanh, 2=sigmoid, 3=gate: g=sigmoid(v); C = g*e1 + (1-g)*e2
__global__ void sgemm2(const float* __restrict__ a0,
                       const float* __restrict__ a1,
                       const float* __restrict__ a2,
                       const float* __restrict__ W,
                       const float* __restrict__ bias,
                       const float* __restrict__ rowscale,
                       const float* __restrict__ e1,
                       const float* __restrict__ e2,
                       float* __restrict__ Cout,
                       int M, int N, int K, int lda, int ldc,
                       long sA, long sW, int bzmask, long sC, int sRS,
                       int act)
{
    __shared__ float As[2][16][68];
    __shared__ float Bs[2][16][64];

    int z = blockIdx.z;
    a0 += (long)z * sA;
    W  += (long)(z & bzmask) * sW;
    Cout += (long)z * sC;
    if (rowscale) rowscale += (long)z * sRS;

    int tid = threadIdx.x;
    int m0 = blockIdx.y * 64, n0 = blockIdx.x * 64;

    // A-load mapping: row = tid/2, k-half = tid&1 (8 k's via 2 float4)
    int ar = tid >> 1, aq = tid & 1;
    // B-load mapping: row = tid/16 (and +8), col4 = (tid&15)*4
    int brow = tid >> 4, bc = (tid & 15) * 4;

    float4 va0, va1, vb0, vb1;
    const float4 z4 = make_float4(0.f, 0.f, 0.f, 0.f);

    int nt = K >> 4;

    // prologue load t=0
    {
        int k0 = 0;
        const float* ap = a0;
        const float* abase = ap + (long)(m0 + ar) * lda + k0 + aq * 8;
        va0 = *(const float4*)abase;
        va1 = *(const float4*)(abase + 4);
        int gn = n0 + bc;
        if (gn < N) {
            const float* bbase = W + (long)brow * N + gn;
            vb0 = *(const float4*)bbase;
            vb1 = *(const float4*)(bbase + 8 * (long)N);
        } else { vb0 = z4; vb1 = z4; }
    }
    {
        As[0][aq*8+0][ar] = va0.x; As[0][aq*8+1][ar] = va0.y;
        As[0][aq*8+2][ar] = va0.z; As[0][aq*8+3][ar] = va0.w;
        As[0][aq*8+4][ar] = va1.x; As[0][aq*8+5][ar] = va1.y;
        As[0][aq*8+6][ar] = va1.z; As[0][aq*8+7][ar] = va1.w;
        *(float4*)&Bs[0][brow][bc] = vb0;
        *(float4*)&Bs[0][brow+8][bc] = vb1;
    }
    __syncthreads();

    int ty = tid >> 4, tx = tid & 15;
    float acc[8][4];
    #pragma unroll
    for (int i = 0; i < 8; i++)
        #pragma unroll
        for (int j = 0; j < 4; j++) acc[i][j] = 0.f;

    for (int t = 0; t < nt; t++) {
        int buf = t & 1;
        if (t + 1 < nt) {
            int k0 = (t + 1) << 4;
            int seg = k0 >> 10;
            int col = k0 - (seg << 10);
            const float* ap = (seg == 0) ? a0 : (seg == 1) ? a1 : a2;
            const float* abase = ap + (long)(m0 + ar) * lda + col + aq * 8;
            va0 = *(const float4*)abase;
            va1 = *(const float4*)(abase + 4);
            int gn = n0 + bc;
            if (gn < N) {
                const float* bbase = W + (long)(k0 + brow) * N + gn;
                vb0 = *(const float4*)bbase;
                vb1 = *(const float4*)(bbase + 8 * (long)N);
            } else { vb0 = z4; vb1 = z4; }
        }

        #pragma unroll
        for (int kk = 0; kk < 16; kk++) {
            float4 am0 = *(const float4*)&As[buf][kk][ty*8];
            float4 am1 = *(const float4*)&As[buf][kk][ty*8+4];
            float4 bv  = *(const float4*)&Bs[buf][kk][tx*4];
            acc[0][0] += am0.x*bv.x; acc[0][1] += am0.x*bv.y; acc[0][2] += am0.x*bv.z; acc[0][3] += am0.x*bv.w;
            acc[1][0] += am0.y*bv.x; acc[1][1] += am0.y*bv.y; acc[1][2] += am0.y*bv.z; acc[1][3] += am0.y*bv.w;
            acc[2][0] += am0.z*bv.x; acc[2][1] += am0.z*bv.y; acc[2][2] += am0.z*bv.z; acc[2][3] += am0.z*bv.w;
            acc[3][0] += am0.w*bv.x; acc[3][1] += am0.w*bv.y; acc[3][2] += am0.w*bv.z; acc[3][3] += am0.w*bv.w;
            acc[4][0] += am1.x*bv.x; acc[4][1] += am1.x*bv.y; acc[4][2] += am1.x*bv.z; acc[4][3] += am1.x*bv.w;
            acc[5][0] += am1.y*bv.x; acc[5][1] += am1.y*bv.y; acc[5][2] += am1.y*bv.z; acc[5][3] += am1.y*bv.w;
            acc[6][0] += am1.z*bv.x; acc[6][1] += am1.z*bv.y; acc[6][2] += am1.z*bv.z; acc[6][3] += am1.z*bv.w;
            acc[7][0] += am1.w*bv.x; acc[7][1] += am1.w*bv.y; acc[7][2] += am1.w*bv.z; acc[7][3] += am1.w*bv.w;
        }

        if (t + 1 < nt) {
            int nbuf = buf ^ 1;
            As[nbuf][aq*8+0][ar] = va0.x; As[nbuf][aq*8+1][ar] = va0.y;
            As[nbuf][aq*8+2][ar] = va0.z; As[nbuf][aq*8+3][ar] = va0.w;
            As[nbuf][aq*8+4][ar] = va1.x; As[nbuf][aq*8+5][ar] = va1.y;
            As[nbuf][aq*8+6][ar] = va1.z; As[nbuf][aq*8+7][ar] = va1.w;
            *(float4*)&Bs[nbuf][brow][bc] = vb0;
            *(float4*)&Bs[nbuf][brow+8][bc] = vb1;
        }
        __syncthreads();
    }

    int gm0 = m0 + ty * 8, gn0 = n0 + tx * 4;
    #pragma unroll
    for (int i = 0; i < 8; i++) {
        int gm = gm0 + i;
        float rs = rowscale ? rowscale[gm] : 1.f;
        #pragma unroll
        for (int j = 0; j < 4; j++) {
            int gn = gn0 + j;
            if (gn >= N) continue;
            float v = acc[i][j];
            if (bias) v += bias[gn];
            v *= rs;
            long off = (long)gm * ldc + gn;
            if (act == 1) v = tanhf(v);
            else if (act == 2) v = 1.f / (1.f + expf(-v));
            else if (act == 3) {
                float g = 1.f / (1.f + expf(-v));
                v = g * e1[off] + (1.f - g) * e2[off];
            }
            Cout[off] = v;
        }
    }
}

// ---------------- fused pairwise scorer (3 j's per thread) ----------------
__global__ void scorer_kernel(const float* __restrict__ lr,
                              const float* __restrict__ dp,
                              const float* __restrict__ Wo,
                              const float* __restrict__ bo,
                              const int* __restrict__ span_begin,
                              const int* __restrict__ span_end,
                              float* __restrict__ scores,
                              int first)
{
    int i = blockIdx.x, b = blockIdx.y;
    int tid = threadIdx.x;  // 128

    __shared__ float s_l[HP_];
    __shared__ float s_dp[NB_][HP_];
    __shared__ float s_w[L_][HP_];
    __shared__ float s_bo[L_];

    const float* lrow = lr + (long)(b * K_ + i) * LRW_;
    for (int x = tid; x < HP_; x += 128) s_l[x] = lrow[x];
    for (int x = tid; x < NB_ * HP_; x += 128) s_dp[x / HP_][x % HP_] = dp[x];
    for (int x = tid; x < L_ * HP_; x += 128) {
        int c = x / HP_, h = x % HP_;
        s_w[c][h] = (h < H_) ? Wo[h * L_ + c] : 0.f;
    }
    if (tid < L_) s_bo[tid] = bo[tid];
    __syncthreads();

    int endi = span_end[b * K_ + i];
    const float* rbase = lr + (long)b * K_ * LRW_ + HP_;

    int j0 = tid, j1 = tid + 128, j2 = tid + 256;

    auto bucket = [&](int j) {
        int d = span_begin[b * K_ + j] - endi;
        int da = d < 0 ? -d : d;
        if (da <= 4) return da;
        int lg = 31 - __clz(da) + 3;
        return lg < (NB_ - 1) ? lg : (NB_ - 1);
    };
    const float* d0 = s_dp[bucket(j0)];
    const float* d1 = s_dp[bucket(j1)];
    const float* d2 = s_dp[bucket(j2)];
    const float* r0 = rbase + (long)j0 * LRW_;
    const float* r1 = rbase + (long)j1 * LRW_;
    const float* r2 = rbase + (long)j2 * LRW_;

    float acc[3][L_];
    #pragma unroll
    for (int c = 0; c < L_; c++) {
        acc[0][c] = s_bo[c]; acc[1][c] = s_bo[c]; acc[2][c] = s_bo[c];
    }

    #pragma unroll 2
    for (int h = 0; h < HP_; h += 4) {
        float4 lv = *(const float4*)(s_l + h);
        float4 rv0 = *(const float4*)(r0 + h);
        float4 rv1 = *(const float4*)(r1 + h);
        float4 rv2 = *(const float4*)(r2 + h);
        float4 dv0 = *(const float4*)(d0 + h);
        float4 dv1 = *(const float4*)(d1 + h);
        float4 dv2 = *(const float4*)(d2 + h);

        float h00 = fmaxf(lv.x + rv0.x + dv0.x, 0.f);
        float h01 = fmaxf(lv.y + rv0.y + dv0.y, 0.f);
        float h02 = fmaxf(lv.z + rv0.z + dv0.z, 0.f);
        float h03 = fmaxf(lv.w + rv0.w + dv0.w, 0.f);
        float h10 = fmaxf(lv.x + rv1.x + dv1.x, 0.f);
        float h11 = fmaxf(lv.y + rv1.y + dv1.y, 0.f);
        float h12 = fmaxf(lv.z + rv1.z + dv1.z, 0.f);
        float h13 = fmaxf(lv.w + rv1.w + dv1.w, 0.f);
        float h20 = fmaxf(lv.x + rv2.x + dv2.x, 0.f);
        float h21 = fmaxf(lv.y + rv2.y + dv2.y, 0.f);
        float h22 = fmaxf(lv.z + rv2.z + dv2.z, 0.f);
        float h23 = fmaxf(lv.w + rv2.w + dv2.w, 0.f);

        #pragma unroll
        for (int c = 0; c < L_; c++) {
            float4 w = *(const float4*)(&s_w[c][h]);
            acc[0][c] += h00 * w.x + h01 * w.y + h02 * w.z + h03 * w.w;
            acc[1][c] += h10 * w.x + h11 * w.y + h12 * w.z + h13 * w.w;
            acc[2][c] += h20 * w.x + h21 * w.y + h22 * w.z + h23 * w.w;
        }
    }

    long rowoff = ((long)(b * K_ + i)) * K_;
    #pragma unroll
    for (int jj = 0; jj < 3; jj++) {
        int j = tid + jj * 128;
        float* out = scores + (rowoff + j) * L_;
        if (first) {
            #pragma unroll
            for (int q = 0; q < 3; q++)
                *(float4*)(out + q * 4) = make_float4(acc[jj][q*4], acc[jj][q*4+1],
                                                      acc[jj][q*4+2], acc[jj][q*4+3]);
        } else {
            #pragma unroll
            for (int q = 0; q < 3; q++) {
                float4 old = *(const float4*)(out + q * 4);
                *(float4*)(out + q * 4) = make_float4(old.x + acc[jj][q*4], old.y + acc[jj][q*4+1],
                                                      old.z + acc[jj][q*4+2], old.w + acc[jj][q*4+3]);
            }
        }
    }
}

// ---------------- probs = sigmoid(max_l scores) * mask ; also transpose ----------------
__global__ void probs_kernel(const float* __restrict__ scores,
                             const float* __restrict__ mask,
                             float* __restrict__ probsAll)
{
    int i = blockIdx.x, b = blockIdx.y;
    for (int j = threadIdx.x; j < K_; j += blockDim.x) {
        const float* s = scores + (((long)(b * K_ + i)) * K_ + j) * L_;
        float m = s[0];
        #pragma unroll
        for (int c = 1; c < L_; c++) m = fmaxf(m, s[c]);
        float p = (1.f / (1.f + expf(-m))) * mask[((long)(b * K_ + i)) * K_ + j];
        probsAll[((long)(b * K_ + i)) * K_ + j] = p;
        probsAll[(long)SZ_P + ((long)(b * K_ + j)) * K_ + i] = p;
    }
}

// ---------------- inverse row sums over probsAll (2*B*K rows) ----------------
__global__ void invsum_kernel(const float* __restrict__ probsAll,
                              float* __restrict__ invAll)
{
    int row = blockIdx.x;
    const float* src = probsAll + (long)row * K_;
    float s = 0.f;
    for (int j = threadIdx.x; j < K_; j += blockDim.x) s += src[j];
    __shared__ float red[4];
    #pragma unroll
    for (int o = 16; o > 0; o >>= 1) s += __shfl_down_sync(0xffffffffu, s, o);
    int wid = threadIdx.x >> 5;
    if ((threadIdx.x & 31) == 0) red[wid] = s;
    __syncthreads();
    if (threadIdx.x == 0) {
        s = red[0] + red[1] + red[2] + red[3];
        invAll[row] = 1.f / (s + 1e-7f);
    }
}

// ---------------- scatter with last-write-wins semantics ----------------
__global__ void scatter_kernel(const float* __restrict__ u,
                               const float* __restrict__ all_span,
                               const int* __restrict__ prune,
                               const int* __restrict__ span_len,
                               float* __restrict__ out_all)
{
    int bk = blockIdx.x;
    int b = bk / K_, k = bk % K_;
    int idx = prune[bk];
    bool last = (k == K_ - 1) || (prune[bk + 1] != idx);
    if (!last) return;
    bool valid = k < span_len[b];
    const float* src = valid ? (u + (long)bk * D_)
                             : (all_span + ((long)b * N_ + idx) * D_);
    float* dst = out_all + ((long)b * N_ + idx) * D_;
    int t = threadIdx.x;
    float4 v = *(const float4*)(src + t * 4);
    *(float4*)(dst + t * 4) = v;
}

// ---------------- host orchestration ----------------
extern "C" void kernel_launch(void* const* d_in, const int* in_sizes, int n_in,
                              void* d_out, int out_size)
{
    const float* span_vecs  = (const float*)d_in[0];
    const float* all_span   = (const float*)d_in[1];
    const int*   span_begin = (const int*)  d_in[2];
    const int*   span_end   = (const int*)  d_in[3];
    const float* mask       = (const float*)d_in[4];
    const int*   prune      = (const int*)  d_in[5];
    const int*   span_len   = (const int*)  d_in[6];
    const float* Wl  = (const float*)d_in[8];
    const float* bl  = (const float*)d_in[9];
    const float* Wr  = (const float*)d_in[10];
    const float* br  = (const float*)d_in[11];
    const float* de  = (const float*)d_in[12];
    const float* Wd  = (const float*)d_in[13];
    const float* bd  = (const float*)d_in[14];
    const float* Wo  = (const float*)d_in[15];
    const float* bo  = (const float*)d_in[16];
    const float* Wff1= (const float*)d_in[17];
    const float* Wff2= (const float*)d_in[18];
    const float* Wg  = (const float*)d_in[19];
    const float* bg  = (const float*)d_in[20];

    float *u, *u2, *lr, *wlr, *blr, *dp, *probsAll, *invAll, *c, *tmp, *ctxt;
    cudaGetSymbolAddress((void**)&u,        g_u);
    cudaGetSymbolAddress((void**)&u2,       g_u2);
    cudaGetSymbolAddress((void**)&lr,       g_lr);
    cudaGetSymbolAddress((void**)&wlr,      g_wlr);
    cudaGetSymbolAddress((void**)&blr,      g_blr);
    cudaGetSymbolAddress((void**)&dp,       g_dp);
    cudaGetSymbolAddress((void**)&probsAll, g_probs);
    cudaGetSymbolAddress((void**)&invAll,   g_inv);
    cudaGetSymbolAddress((void**)&c,        g_c);
    cudaGetSymbolAddress((void**)&tmp,      g_tmp);
    cudaGetSymbolAddress((void**)&ctxt,     g_ctxt);

    float* out_all = (float*)d_out;
    float* out_u   = out_all + (size_t)B_ * N_ * D_;
    float* out_sc  = out_u   + (size_t)B_ * K_ * D_;

    const int M = B_ * K_;  // 768

    cudaMemcpyAsync(u, span_vecs, sizeof(float) * SZ_U, cudaMemcpyDeviceToDevice);
    init_kernel<<<128, 256>>>(de, Wd, bd, Wl, bl, Wr, br, dp, wlr, blr);

    float* ucur = u;
    float* unext = u2;

    // initial l|r projection + scorer
    sgemm2<<<dim3(5, 12, 1), 128>>>(ucur, ucur, ucur, wlr, blr, nullptr, nullptr, nullptr,
                                    lr, M, LRW_, D_, D_, LRW_, 0, 0, 0, 0, 0, 0);
    scorer_kernel<<<dim3(K_, B_), 128>>>(lr, dp, Wo, bo, span_begin, span_end, out_sc, 1);

    for (int it = 0; it < 2; it++) {
        probs_kernel<<<dim3(K_, B_), 128>>>(out_sc, mask, probsAll);
        invsum_kernel<<<2 * B_ * K_, 128>>>(probsAll, invAll);

        // c[z] = (probsAll[z] @ u[z&1]) * invAll[z], z=0..3 -> [c1 b0,b1 | c2 b0,b1]
        sgemm2<<<dim3(16, 6, 4), 128>>>(probsAll, probsAll, probsAll, ucur, nullptr, invAll,
                                        nullptr, nullptr, c,
                                        K_, D_, K_, K_, D_,
                                        (long)K_*K_, (long)K_*D_, 1, (long)K_*D_, K_, 0);

        // tmp = tanh([u|c1|c2] @ Wff1)
        sgemm2<<<dim3(16, 12, 1), 128>>>(ucur, c, c + SZ_U, Wff1, nullptr, nullptr,
                                         nullptr, nullptr, tmp,
                                         M, D_, 3 * D_, D_, D_, 0, 0, 0, 0, 0, 1);
        // ctxt = tmp @ Wff2
        sgemm2<<<dim3(16, 12, 1), 128>>>(tmp, tmp, tmp, Wff2, nullptr, nullptr,
                                         nullptr, nullptr, ctxt,
                                         M, D_, D_, D_, D_, 0, 0, 0, 0, 0, 0);
        // unext = g*u + (1-g)*ctxt, g = sigmoid([u|ctxt] @ Wg + bg)
        sgemm2<<<dim3(16, 12, 1), 128>>>(ucur, ctxt, ctxt, Wg, bg, nullptr,
                                         ucur, ctxt, unext,
                                         M, D_, 2 * D_, D_, D_, 0, 0, 0, 0, 0, 3);
        // swap
        float* t2 = ucur; ucur = unext; unext = t2;

        // re-project + scorer (residual accumulate)
        sgemm2<<<dim3(5, 12, 1), 128>>>(ucur, ucur, ucur, wlr, blr, nullptr, nullptr, nullptr,
                                        lr, M, LRW_, D_, D_, LRW_, 0, 0, 0, 0, 0, 0);
        scorer_kernel<<<dim3(K_, B_), 128>>>(lr, dp, Wo, bo, span_begin, span_end, out_sc, 0);
    }

    // outputs: update_all, u, scores (scores already written in place)
    cudaMemcpyAsync(out_all, all_span, sizeof(float) * (size_t)B_ * N_ * D_, cudaMemcpyDeviceToDevice);
    scatter_kernel<<<B_ * K_, 256>>>(ucur, all_span, prune, span_len, out_all);
    cudaMemcpyAsync(out_u, ucur, sizeof(float) * SZ_U, cudaMemcpyDeviceToDevice);
}

// round 3
// speedup vs baseline: 2.1571x; 1.5905x over previous
#include <cuda_runtime.h>
#include <math.h>

// ---------------- problem constants ----------------
#define B_    2
#define K_    384
#define N_    4096
#define D_    1024
#define H_    150
#define HP_   152     // padded H
#define LRWP_ 384     // l|r concatenated row width, padded to tile multiple
#define L_    12
#define NB_   10
#define DE_   20

#define SZ_U   (B_*K_*D_)       // 786432
#define SZ_P   (B_*K_*K_)       // 294912
#define SZ_S   (B_*K_)          // 768

// ---------------- device scratch (static, no allocs) ----------------
__device__ float g_u[SZ_U];
__device__ float g_u2[SZ_U];
__device__ float g_lr[B_*K_*LRWP_];
__device__ float g_wlr[D_*LRWP_];
__device__ float g_blr[LRWP_];
__device__ float g_dp[NB_*HP_];
__device__ float g_probs[2*SZ_P];     // [probs b0, probs b1, probsT b0, probsT b1]
__device__ float g_inv[2*SZ_S];
__device__ float g_c[2*SZ_U];         // [c1 (b0,b1), c2 (b0,b1)]
__device__ float g_tmp[SZ_U];
__device__ float g_ctxt[SZ_U];

__device__ __forceinline__ unsigned f2t(float x) {
    unsigned r;
    asm("cvt.rna.tf32.f32 %0, %1;" : "=r"(r) : "f"(x));
    return r;
}

// ---------------- init: dp table + W_lr / b_lr concat (padded to 384) ----------------
__global__ void init_kernel(const float* __restrict__ dist_emb,
                            const float* __restrict__ Wd,
                            const float* __restrict__ bd,
                            const float* __restrict__ Wl,
                            const float* __restrict__ bl,
                            const float* __restrict__ Wr,
                            const float* __restrict__ br,
                            float* __restrict__ dp,
                            float* __restrict__ wlr,
                            float* __restrict__ blr)
{
    int tid = blockIdx.x * blockDim.x + threadIdx.x;
    int nthr = gridDim.x * blockDim.x;
    for (int idx = tid; idx < NB_*HP_; idx += nthr) {
        int n = idx / HP_, h = idx % HP_;
        float v = 0.f;
        if (h < H_) {
            v = bd[h];
            #pragma unroll
            for (int t = 0; t < DE_; t++)
                v += dist_emb[n * DE_ + t] * Wd[t * H_ + h];
        }
        dp[idx] = v;
    }
    for (int idx = tid; idx < D_*LRWP_; idx += nthr) {
        int k = idx / LRWP_, c = idx % LRWP_;
        float v = 0.f;
        if (c < H_) v = Wl[k * H_ + c];
        else if (c >= HP_ && c < HP_ + H_) v = Wr[k * H_ + (c - HP_)];
        wlr[idx] = v;
    }
    for (int c = tid; c < LRWP_; c += nthr) {
        float v = 0.f;
        if (c < H_) v = bl[c];
        else if (c >= HP_ && c < HP_ + H_) v = br[c - HP_];
        blr[c] = v;
    }
}

// ---------------- tf32 tensor-core GEMM ----------------
// Block tile 64x128, 4 warps, warp tile 32x64 (2x8 m16n8k8), K-step 16, dbl-buffered.
// Requires: M % 64 == 0, N % 128 == 0, K % 16 == 0. A segmented along K in
// 1024-wide chunks (a0,a1,a2), each with row stride lda.
// C = act( rowscale * (A @ W + bias) )
// act: 0=none, 1=tanh, 2=sigmoid, 3=gate: g=sigmoid(v); C = g*e1 + (1-g)*e2
__global__ void __launch_bounds__(128)
mma_gemm(const float* __restrict__ a0,
         const float* __restrict__ a1,
         const float* __restrict__ a2,
         const float* __restrict__ W,
         const float* __restrict__ bias,
         const float* __restrict__ rowscale,
         const float* __restrict__ e1,
         const float* __restrict__ e2,
         float* __restrict__ Cout,
         int M, int N, int K, int lda, int ldc,
         long sA, long sW, int bzmask, long sC, int sRS,
         int act)
{
    __shared__ unsigned As[2][64][20];    // [k-buf][row][k], stride 20 -> conflict-free frags
    __shared__ unsigned Bs[2][16][136];   // [k-buf][k][col], stride 136 -> conflict-free frags

    int z = blockIdx.z;
    a0 += (long)z * sA;
    W  += (long)(z & bzmask) * sW;
    Cout += (long)z * sC;
    if (rowscale) rowscale += (long)z * sRS;

    int tid = threadIdx.x;
    int warp = tid >> 5, lane = tid & 31;
    int m0 = blockIdx.y * 64, n0 = blockIdx.x * 128;
    int wm = (warp >> 1) * 32, wn = (warp & 1) * 64;

    int ar = tid >> 1, aq = tid & 1;        // A ldg: row ar, cols aq*8..aq*8+7
    int br = tid >> 4, bc = (tid & 15) * 8; // B ldg: rows br,br+8, cols bc..bc+7

    float4 fa0, fa1, fb00, fb01, fb10, fb11;

    // prologue: load tile t=0
    {
        const float* ab = a0 + (long)(m0 + ar) * lda + aq * 8;
        fa0 = *(const float4*)ab;
        fa1 = *(const float4*)(ab + 4);
        const float* bb = W + (long)br * N + n0 + bc;
        fb00 = *(const float4*)bb;
        fb01 = *(const float4*)(bb + 4);
        const float* bb2 = bb + 8l * N;
        fb10 = *(const float4*)bb2;
        fb11 = *(const float4*)(bb2 + 4);
    }
    {
        uint4 v0 = make_uint4(f2t(fa0.x), f2t(fa0.y), f2t(fa0.z), f2t(fa0.w));
        uint4 v1 = make_uint4(f2t(fa1.x), f2t(fa1.y), f2t(fa1.z), f2t(fa1.w));
        *(uint4*)&As[0][ar][aq*8]     = v0;
        *(uint4*)&As[0][ar][aq*8 + 4] = v1;
        *(uint4*)&Bs[0][br][bc]       = make_uint4(f2t(fb00.x), f2t(fb00.y), f2t(fb00.z), f2t(fb00.w));
        *(uint4*)&Bs[0][br][bc + 4]   = make_uint4(f2t(fb01.x), f2t(fb01.y), f2t(fb01.z), f2t(fb01.w));
        *(uint4*)&Bs[0][br+8][bc]     = make_uint4(f2t(fb10.x), f2t(fb10.y), f2t(fb10.z), f2t(fb10.w));
        *(uint4*)&Bs[0][br+8][bc + 4] = make_uint4(f2t(fb11.x), f2t(fb11.y), f2t(fb11.z), f2t(fb11.w));
    }
    __syncthreads();

    float acc[2][8][4];
    #pragma unroll
    for (int i = 0; i < 2; i++)
        #pragma unroll
        for (int j = 0; j < 8; j++)
            #pragma unroll
            for (int q = 0; q < 4; q++) acc[i][j][q] = 0.f;

    int nt = K >> 4;
    for (int t = 0; t < nt; t++) {
        int buf = t & 1;
        if (t + 1 < nt) {
            int k0 = (t + 1) << 4;
            int seg = k0 >> 10, col = k0 & 1023;
            const float* ap = (seg == 0) ? a0 : (seg == 1) ? a1 : a2;
            const float* ab = ap + (long)(m0 + ar) * lda + col + aq * 8;
            fa0 = *(const float4*)ab;
            fa1 = *(const float4*)(ab + 4);
            const float* bb = W + (long)(k0 + br) * N + n0 + bc;
            fb00 = *(const float4*)bb;
            fb01 = *(const float4*)(bb + 4);
            const float* bb2 = bb + 8l * N;
            fb10 = *(const float4*)bb2;
            fb11 = *(const float4*)(bb2 + 4);
        }

        #pragma unroll
        for (int kx = 0; kx < 2; kx++) {
            unsigned a[2][4];
            #pragma unroll
            for (int mt = 0; mt < 2; mt++) {
                int r_ = wm + mt * 16 + (lane >> 2);
                int c_ = kx * 8 + (lane & 3);
                a[mt][0] = As[buf][r_][c_];
                a[mt][1] = As[buf][r_ + 8][c_];
                a[mt][2] = As[buf][r_][c_ + 4];
                a[mt][3] = As[buf][r_ + 8][c_ + 4];
            }
            #pragma unroll
            for (int ct = 0; ct < 8; ct++) {
                unsigned b0 = Bs[buf][kx*8 + (lane & 3)][wn + ct*8 + (lane >> 2)];
                unsigned b1 = Bs[buf][kx*8 + (lane & 3) + 4][wn + ct*8 + (lane >> 2)];
                #pragma unroll
                for (int mt = 0; mt < 2; mt++) {
                    asm volatile(
                        "mma.sync.aligned.m16n8k8.row.col.f32.tf32.tf32.f32 "
                        "{%0,%1,%2,%3}, {%4,%5,%6,%7}, {%8,%9}, {%0,%1,%2,%3};"
                        : "+f"(acc[mt][ct][0]), "+f"(acc[mt][ct][1]),
                          "+f"(acc[mt][ct][2]), "+f"(acc[mt][ct][3])
                        : "r"(a[mt][0]), "r"(a[mt][1]), "r"(a[mt][2]), "r"(a[mt][3]),
                          "r"(b0), "r"(b1));
                }
            }
        }

        if (t + 1 < nt) {
            int nb = buf ^ 1;
            *(uint4*)&As[nb][ar][aq*8]     = make_uint4(f2t(fa0.x), f2t(fa0.y), f2t(fa0.z), f2t(fa0.w));
            *(uint4*)&As[nb][ar][aq*8 + 4] = make_uint4(f2t(fa1.x), f2t(fa1.y), f2t(fa1.z), f2t(fa1.w));
            *(uint4*)&Bs[nb][br][bc]       = make_uint4(f2t(fb00.x), f2t(fb00.y), f2t(fb00.z), f2t(fb00.w));
            *(uint4*)&Bs[nb][br][bc + 4]   = make_uint4(f2t(fb01.x), f2t(fb01.y), f2t(fb01.z), f2t(fb01.w));
            *(uint4*)&Bs[nb][br+8][bc]     = make_uint4(f2t(fb10.x), f2t(fb10.y), f2t(fb10.z), f2t(fb10.w));
            *(uint4*)&Bs[nb][br+8][bc + 4] = make_uint4(f2t(fb11.x), f2t(fb11.y), f2t(fb11.z), f2t(fb11.w));
        }
        __syncthreads();
    }

    // epilogue
    #pragma unroll
    for (int mt = 0; mt < 2; mt++) {
        #pragma unroll
        for (int rh = 0; rh < 2; rh++) {
            int gm = m0 + wm + mt * 16 + (lane >> 2) + rh * 8;
            float rs = rowscale ? rowscale[gm] : 1.f;
            #pragma unroll
            for (int ct = 0; ct < 8; ct++) {
                int gn = n0 + wn + ct * 8 + (lane & 3) * 2;
                float v0 = acc[mt][ct][rh * 2 + 0];
                float v1 = acc[mt][ct][rh * 2 + 1];
                if (bias) { v0 += bias[gn]; v1 += bias[gn + 1]; }
                v0 *= rs; v1 *= rs;
                long off = (long)gm * ldc + gn;
                if (act == 1) { v0 = tanhf(v0); v1 = tanhf(v1); }
                else if (act == 2) {
                    v0 = 1.f / (1.f + expf(-v0));
                    v1 = 1.f / (1.f + expf(-v1));
                }
                else if (act == 3) {
                    float g0 = 1.f / (1.f + expf(-v0));
                    float g1 = 1.f / (1.f + expf(-v1));
                    v0 = g0 * e1[off]     + (1.f - g0) * e2[off];
                    v1 = g1 * e1[off + 1] + (1.f - g1) * e2[off + 1];
                }
                *(float2*)(Cout + off) = make_float2(v0, v1);
            }
        }
    }
}

// ---------------- fused pairwise scorer (3 j's per thread, fp32) ----------------
__global__ void scorer_kernel(const float* __restrict__ lr,
                              const float* __restrict__ dp,
                              const float* __restrict__ Wo,
                              const float* __restrict__ bo,
                              const int* __restrict__ span_begin,
                              const int* __restrict__ span_end,
                              float* __restrict__ scores,
                              int first)
{
    int i = blockIdx.x, b = blockIdx.y;
    int tid = threadIdx.x;  // 128

    __shared__ float s_l[HP_];
    __shared__ float s_dp[NB_][HP_];
    __shared__ float s_w[L_][HP_];
    __shared__ float s_bo[L_];

    const float* lrow = lr + (long)(b * K_ + i) * LRWP_;
    for (int x = tid; x < HP_; x += 128) s_l[x] = lrow[x];
    for (int x = tid; x < NB_ * HP_; x += 128) s_dp[x / HP_][x % HP_] = dp[x];
    for (int x = tid; x < L_ * HP_; x += 128) {
        int c = x / HP_, h = x % HP_;
        s_w[c][h] = (h < H_) ? Wo[h * L_ + c] : 0.f;
    }
    if (tid < L_) s_bo[tid] = bo[tid];
    __syncthreads();

    int endi = span_end[b * K_ + i];
    const float* rbase = lr + (long)b * K_ * LRWP_ + HP_;

    int j0 = tid, j1 = tid + 128, j2 = tid + 256;

    auto bucket = [&](int j) {
        int d = span_begin[b * K_ + j] - endi;
        int da = d < 0 ? -d : d;
        if (da <= 4) return da;
        int lg = 31 - __clz(da) + 3;
        return lg < (NB_ - 1) ? lg : (NB_ - 1);
    };
    const float* d0 = s_dp[bucket(j0)];
    const float* d1 = s_dp[bucket(j1)];
    const float* d2 = s_dp[bucket(j2)];
    const float* r0 = rbase + (long)j0 * LRWP_;
    const float* r1 = rbase + (long)j1 * LRWP_;
    const float* r2 = rbase + (long)j2 * LRWP_;

    float acc[3][L_];
    #pragma unroll
    for (int c = 0; c < L_; c++) {
        acc[0][c] = s_bo[c]; acc[1][c] = s_bo[c]; acc[2][c] = s_bo[c];
    }

    #pragma unroll 2
    for (int h = 0; h < HP_; h += 4) {
        float4 lv = *(const float4*)(s_l + h);
        float4 rv0 = *(const float4*)(r0 + h);
        float4 rv1 = *(const float4*)(r1 + h);
        float4 rv2 = *(const float4*)(r2 + h);
        float4 dv0 = *(const float4*)(d0 + h);
        float4 dv1 = *(const float4*)(d1 + h);
        float4 dv2 = *(const float4*)(d2 + h);

        float h00 = fmaxf(lv.x + rv0.x + dv0.x, 0.f);
        float h01 = fmaxf(lv.y + rv0.y + dv0.y, 0.f);
        float h02 = fmaxf(lv.z + rv0.z + dv0.z, 0.f);
        float h03 = fmaxf(lv.w + rv0.w + dv0.w, 0.f);
        float h10 = fmaxf(lv.x + rv1.x + dv1.x, 0.f);
        float h11 = fmaxf(lv.y + rv1.y + dv1.y, 0.f);
        float h12 = fmaxf(lv.z + rv1.z + dv1.z, 0.f);
        float h13 = fmaxf(lv.w + rv1.w + dv1.w, 0.f);
        float h20 = fmaxf(lv.x + rv2.x + dv2.x, 0.f);
        float h21 = fmaxf(lv.y + rv2.y + dv2.y, 0.f);
        float h22 = fmaxf(lv.z + rv2.z + dv2.z, 0.f);
        float h23 = fmaxf(lv.w + rv2.w + dv2.w, 0.f);

        #pragma unroll
        for (int c = 0; c < L_; c++) {
            float4 w = *(const float4*)(&s_w[c][h]);
            acc[0][c] += h00 * w.x + h01 * w.y + h02 * w.z + h03 * w.w;
            acc[1][c] += h10 * w.x + h11 * w.y + h12 * w.z + h13 * w.w;
            acc[2][c] += h20 * w.x + h21 * w.y + h22 * w.z + h23 * w.w;
        }
    }

    long rowoff = ((long)(b * K_ + i)) * K_;
    #pragma unroll
    for (int jj = 0; jj < 3; jj++) {
        int j = tid + jj * 128;
        float* out = scores + (rowoff + j) * L_;
        if (first) {
            #pragma unroll
            for (int q = 0; q < 3; q++)
                *(float4*)(out + q * 4) = make_float4(acc[jj][q*4], acc[jj][q*4+1],
                                                      acc[jj][q*4+2], acc[jj][q*4+3]);
        } else {
            #pragma unroll
            for (int q = 0; q < 3; q++) {
                float4 old = *(const float4*)(out + q * 4);
                *(float4*)(out + q * 4) = make_float4(old.x + acc[jj][q*4], old.y + acc[jj][q*4+1],
                                                      old.z + acc[jj][q*4+2], old.w + acc[jj][q*4+3]);
            }
        }
    }
}

// ---------------- probs = sigmoid(max_l scores) * mask ; also transpose ----------------
__global__ void probs_kernel(const float* __restrict__ scores,
                             const float* __restrict__ mask,
                             float* __restrict__ probsAll)
{
    int i = blockIdx.x, b = blockIdx.y;
    for (int j = threadIdx.x; j < K_; j += blockDim.x) {
        const float* s = scores + (((long)(b * K_ + i)) * K_ + j) * L_;
        float m = s[0];
        #pragma unroll
        for (int c = 1; c < L_; c++) m = fmaxf(m, s[c]);
        float p = (1.f / (1.f + expf(-m))) * mask[((long)(b * K_ + i)) * K_ + j];
        probsAll[((long)(b * K_ + i)) * K_ + j] = p;
        probsAll[(long)SZ_P + ((long)(b * K_ + j)) * K_ + i] = p;
    }
}

// ---------------- inverse row sums over probsAll (2*B*K rows) ----------------
__global__ void invsum_kernel(const float* __restrict__ probsAll,
                              float* __restrict__ invAll)
{
    int row = blockIdx.x;
    const float* src = probsAll + (long)row * K_;
    float s = 0.f;
    for (int j = threadIdx.x; j < K_; j += blockDim.x) s += src[j];
    __shared__ float red[4];
    #pragma unroll
    for (int o = 16; o > 0; o >>= 1) s += __shfl_down_sync(0xffffffffu, s, o);
    int wid = threadIdx.x >> 5;
    if ((threadIdx.x & 31) == 0) red[wid] = s;
    __syncthreads();
    if (threadIdx.x == 0) {
        s = red[0] + red[1] + red[2] + red[3];
        invAll[row] = 1.f / (s + 1e-7f);
    }
}

// ---------------- scatter with last-write-wins semantics ----------------
__global__ void scatter_kernel(const float* __restrict__ u,
                               const float* __restrict__ all_span,
                               const int* __restrict__ prune,
                               const int* __restrict__ span_len,
                               float* __restrict__ out_all)
{
    int bk = blockIdx.x;
    int b = bk / K_, k = bk % K_;
    int idx = prune[bk];
    bool last = (k == K_ - 1) || (prune[bk + 1] != idx);
    if (!last) return;
    bool valid = k < span_len[b];
    const float* src = valid ? (u + (long)bk * D_)
                             : (all_span + ((long)b * N_ + idx) * D_);
    float* dst = out_all + ((long)b * N_ + idx) * D_;
    int t = threadIdx.x;
    float4 v = *(const float4*)(src + t * 4);
    *(float4*)(dst + t * 4) = v;
}

// ---------------- host orchestration ----------------
extern "C" void kernel_launch(void* const* d_in, const int* in_sizes, int n_in,
                              void* d_out, int out_size)
{
    const float* span_vecs  = (const float*)d_in[0];
    const float* all_span   = (const float*)d_in[1];
    const int*   span_begin = (const int*)  d_in[2];
    const int*   span_end   = (const int*)  d_in[3];
    const float* mask       = (const float*)d_in[4];
    const int*   prune      = (const int*)  d_in[5];
    const int*   span_len   = (const int*)  d_in[6];
    const float* Wl  = (const float*)d_in[8];
    const float* bl  = (const float*)d_in[9];
    const float* Wr  = (const float*)d_in[10];
    const float* br  = (const float*)d_in[11];
    const float* de  = (const float*)d_in[12];
    const float* Wd  = (const float*)d_in[13];
    const float* bd  = (const float*)d_in[14];
    const float* Wo  = (const float*)d_in[15];
    const float* bo  = (const float*)d_in[16];
    const float* Wff1= (const float*)d_in[17];
    const float* Wff2= (const float*)d_in[18];
    const float* Wg  = (const float*)d_in[19];
    const float* bg  = (const float*)d_in[20];

    float *u, *u2, *lr, *wlr, *blr, *dp, *probsAll, *invAll, *c, *tmp, *ctxt;
    cudaGetSymbolAddress((void**)&u,        g_u);
    cudaGetSymbolAddress((void**)&u2,       g_u2);
    cudaGetSymbolAddress((void**)&lr,       g_lr);
    cudaGetSymbolAddress((void**)&wlr,      g_wlr);
    cudaGetSymbolAddress((void**)&blr,      g_blr);
    cudaGetSymbolAddress((void**)&dp,       g_dp);
    cudaGetSymbolAddress((void**)&probsAll, g_probs);
    cudaGetSymbolAddress((void**)&invAll,   g_inv);
    cudaGetSymbolAddress((void**)&c,        g_c);
    cudaGetSymbolAddress((void**)&tmp,      g_tmp);
    cudaGetSymbolAddress((void**)&ctxt,     g_ctxt);

    float* out_all = (float*)d_out;
    float* out_u   = out_all + (size_t)B_ * N_ * D_;
    float* out_sc  = out_u   + (size_t)B_ * K_ * D_;

    const int M = B_ * K_;  // 768

    cudaMemcpyAsync(u, span_vecs, sizeof(float) * SZ_U, cudaMemcpyDeviceToDevice);
    init_kernel<<<128, 256>>>(de, Wd, bd, Wl, bl, Wr, br, dp, wlr, blr);

    float* ucur = u;
    float* unext = u2;

    // initial l|r projection + scorer
    mma_gemm<<<dim3(3, 12, 1), 128>>>(ucur, ucur, ucur, wlr, blr, nullptr, nullptr, nullptr,
                                      lr, M, LRWP_, D_, D_, LRWP_, 0, 0, 0, 0, 0, 0);
    scorer_kernel<<<dim3(K_, B_), 128>>>(lr, dp, Wo, bo, span_begin, span_end, out_sc, 1);

    for (int it = 0; it < 2; it++) {
        probs_kernel<<<dim3(K_, B_), 128>>>(out_sc, mask, probsAll);
        invsum_kernel<<<2 * B_ * K_, 128>>>(probsAll, invAll);

        // c[z] = (probsAll[z] @ u[z&1]) * invAll[z], z=0..3 -> [c1 b0,b1 | c2 b0,b1]
        mma_gemm<<<dim3(8, 6, 4), 128>>>(probsAll, probsAll, probsAll, ucur, nullptr, invAll,
                                         nullptr, nullptr, c,
                                         K_, D_, K_, K_, D_,
                                         (long)K_*K_, (long)K_*D_, 1, (long)K_*D_, K_, 0);

        // tmp = tanh([u|c1|c2] @ Wff1)
        mma_gemm<<<dim3(8, 12, 1), 128>>>(ucur, c, c + SZ_U, Wff1, nullptr, nullptr,
                                          nullptr, nullptr, tmp,
                                          M, D_, 3 * D_, D_, D_, 0, 0, 0, 0, 0, 1);
        // ctxt = tmp @ Wff2
        mma_gemm<<<dim3(8, 12, 1), 128>>>(tmp, tmp, tmp, Wff2, nullptr, nullptr,
                                          nullptr, nullptr, ctxt,
                                          M, D_, D_, D_, D_, 0, 0, 0, 0, 0, 0);
        // unext = g*u + (1-g)*ctxt, g = sigmoid([u|ctxt] @ Wg + bg)
        mma_gemm<<<dim3(8, 12, 1), 128>>>(ucur, ctxt, ctxt, Wg, bg, nullptr,
                                          ucur, ctxt, unext,
                                          M, D_, 2 * D_, D_, D_, 0, 0, 0, 0, 0, 3);
        float* t2 = ucur; ucur = unext; unext = t2;

        // re-project + scorer (residual accumulate)
        mma_gemm<<<dim3(3, 12, 1), 128>>>(ucur, ucur, ucur, wlr, blr, nullptr, nullptr, nullptr,
                                          lr, M, LRWP_, D_, D_, LRWP_, 0, 0, 0, 0, 0, 0);
        scorer_kernel<<<dim3(K_, B_), 128>>>(lr, dp, Wo, bo, span_begin, span_end, out_sc, 0);
    }

    // outputs: update_all, u, scores (scores already written in place)
    cudaMemcpyAsync(out_all, all_span, sizeof(float) * (size_t)B_ * N_ * D_, cudaMemcpyDeviceToDevice);
    scatter_kernel<<<B_ * K_, 256>>>(ucur, all_span, prune, span_len, out_all);
    cudaMemcpyAsync(out_u, ucur, sizeof(float) * SZ_U, cudaMemcpyDeviceToDevice);
}

// round 4
// speedup vs baseline: 2.4813x; 1.1503x over previous
#include <cuda_runtime.h>
#include <math.h>

// ---------------- problem constants ----------------
#define B_    2
#define K_    384
#define N_    4096
#define D_    1024
#define H_    150
#define HP_   152     // padded H
#define LRWP_ 384     // l|r concatenated row width, padded to tile multiple
#define L_    12
#define NB_   10
#define DE_   20

#define SZ_U   (B_*K_*D_)       // 786432
#define SZ_P   (B_*K_*K_)       // 294912
#define SZ_S   (B_*K_)          // 768

// ---------------- device scratch (static, no allocs) ----------------
__device__ float g_u[SZ_U];
__device__ float g_u2[SZ_U];
__device__ float g_lr[B_*K_*LRWP_];
__device__ float g_wlr[D_*LRWP_];
__device__ float g_blr[LRWP_];
__device__ float g_dp[NB_*HP_];
__device__ float g_probs[2*SZ_P];     // [probs b0, probs b1, probsT b0, probsT b1]
__device__ float g_inv[2*SZ_S];
__device__ float g_c[2*SZ_U];         // [c1 (b0,b1), c2 (b0,b1)]
__device__ float g_tmp[SZ_U];
__device__ float g_ctxt[SZ_U];

__device__ __forceinline__ unsigned f2t(float x) {
    unsigned r;
    asm("cvt.rna.tf32.f32 %0, %1;" : "=r"(r) : "f"(x));
    return r;
}

// ---------------- init: dp table + W_lr / b_lr concat (padded to 384) ----------------
__global__ void init_kernel(const float* __restrict__ dist_emb,
                            const float* __restrict__ Wd,
                            const float* __restrict__ bd,
                            const float* __restrict__ Wl,
                            const float* __restrict__ bl,
                            const float* __restrict__ Wr,
                            const float* __restrict__ br,
                            float* __restrict__ dp,
                            float* __restrict__ wlr,
                            float* __restrict__ blr)
{
    int tid = blockIdx.x * blockDim.x + threadIdx.x;
    int nthr = gridDim.x * blockDim.x;
    for (int idx = tid; idx < NB_*HP_; idx += nthr) {
        int n = idx / HP_, h = idx % HP_;
        float v = 0.f;
        if (h < H_) {
            v = bd[h];
            #pragma unroll
            for (int t = 0; t < DE_; t++)
                v += dist_emb[n * DE_ + t] * Wd[t * H_ + h];
        }
        dp[idx] = v;
    }
    for (int idx = tid; idx < D_*LRWP_; idx += nthr) {
        int k = idx / LRWP_, c = idx % LRWP_;
        float v = 0.f;
        if (c < H_) v = Wl[k * H_ + c];
        else if (c >= HP_ && c < HP_ + H_) v = Wr[k * H_ + (c - HP_)];
        wlr[idx] = v;
    }
    for (int c = tid; c < LRWP_; c += nthr) {
        float v = 0.f;
        if (c < H_) v = bl[c];
        else if (c >= HP_ && c < HP_ + H_) v = br[c - HP_];
        blr[c] = v;
    }
}

// ---------------- tf32 tensor-core GEMM, BM x 64 block tile ----------------
// 128 threads, 4 warps (2x2), warp tile (BM/2) x 32, K-step 16, double buffered.
// Requires: M % BM == 0, N % 64 == 0, K % 16 == 0.
// A segmented along K in 1024-wide chunks (a0,a1,a2), each with row stride lda.
// C = act( rowscale * (A @ W + bias) )
// act: 0=none, 1=tanh, 2=sigmoid, 3=gate: g=sigmoid(v); C = g*e1 + (1-g)*e2
template<int BM>
__global__ void __launch_bounds__(128, 2)
mma_gemm(const float* __restrict__ a0,
         const float* __restrict__ a1,
         const float* __restrict__ a2,
         const float* __restrict__ W,
         const float* __restrict__ bias,
         const float* __restrict__ rowscale,
         const float* __restrict__ e1,
         const float* __restrict__ e2,
         float* __restrict__ Cout,
         int M, int N, int K, int lda, int ldc,
         long sA, long sW, int bzmask, long sC, int sRS,
         int act)
{
    constexpr int MT = BM / 32;           // 16-row m-tiles per warp (1 or 2)
    __shared__ unsigned As[2][BM][20];    // stride 20 -> conflict-free frags
    __shared__ unsigned Bs[2][16][72];    // stride 72 -> conflict-free frags

    int z = blockIdx.z;
    a0 += (long)z * sA;
    W  += (long)(z & bzmask) * sW;
    Cout += (long)z * sC;
    if (rowscale) rowscale += (long)z * sRS;

    int tid = threadIdx.x;
    int warp = tid >> 5, lane = tid & 31;
    int m0 = blockIdx.y * BM, n0 = blockIdx.x * 64;
    int wm = (warp >> 1) * (BM / 2), wn = (warp & 1) * 32;

    // A ldg mapping
    int ar, aq;
    if (BM == 64) { ar = tid >> 1; aq = tid & 1; }   // 2 float4 (cols aq*8..aq*8+7)
    else          { ar = tid >> 2; aq = tid & 3; }   // 1 float4 (cols aq*4..aq*4+3)
    // B ldg mapping: rows br,br+8, cols bc..bc+3
    int brw = tid >> 4, bc = (tid & 15) * 4;

    float4 fa0, fa1, fb0, fb1;

    // prologue: load tile t=0
    {
        if (BM == 64) {
            const float* ab = a0 + (long)(m0 + ar) * lda + aq * 8;
            fa0 = *(const float4*)ab;
            fa1 = *(const float4*)(ab + 4);
        } else {
            const float* ab = a0 + (long)(m0 + ar) * lda + aq * 4;
            fa0 = *(const float4*)ab;
        }
        const float* bb = W + (long)brw * N + n0 + bc;
        fb0 = *(const float4*)bb;
        fb1 = *(const float4*)(bb + 8l * N);
    }
    {
        if (BM == 64) {
            *(uint4*)&As[0][ar][aq*8]     = make_uint4(f2t(fa0.x), f2t(fa0.y), f2t(fa0.z), f2t(fa0.w));
            *(uint4*)&As[0][ar][aq*8 + 4] = make_uint4(f2t(fa1.x), f2t(fa1.y), f2t(fa1.z), f2t(fa1.w));
        } else {
            *(uint4*)&As[0][ar][aq*4]     = make_uint4(f2t(fa0.x), f2t(fa0.y), f2t(fa0.z), f2t(fa0.w));
        }
        *(uint4*)&Bs[0][brw][bc]   = make_uint4(f2t(fb0.x), f2t(fb0.y), f2t(fb0.z), f2t(fb0.w));
        *(uint4*)&Bs[0][brw+8][bc] = make_uint4(f2t(fb1.x), f2t(fb1.y), f2t(fb1.z), f2t(fb1.w));
    }
    __syncthreads();

    float acc[MT][4][4];
    #pragma unroll
    for (int i = 0; i < MT; i++)
        #pragma unroll
        for (int j = 0; j < 4; j++)
            #pragma unroll
            for (int q = 0; q < 4; q++) acc[i][j][q] = 0.f;

    int nt = K >> 4;
    for (int t = 0; t < nt; t++) {
        int buf = t & 1;
        if (t + 1 < nt) {
            int k0 = (t + 1) << 4;
            int seg = k0 >> 10, col = k0 & 1023;
            const float* ap = (seg == 0) ? a0 : (seg == 1) ? a1 : a2;
            if (BM == 64) {
                const float* ab = ap + (long)(m0 + ar) * lda + col + aq * 8;
                fa0 = *(const float4*)ab;
                fa1 = *(const float4*)(ab + 4);
            } else {
                const float* ab = ap + (long)(m0 + ar) * lda + col + aq * 4;
                fa0 = *(const float4*)ab;
            }
            const float* bb = W + (long)(k0 + brw) * N + n0 + bc;
            fb0 = *(const float4*)bb;
            fb1 = *(const float4*)(bb + 8l * N);
        }

        #pragma unroll
        for (int kx = 0; kx < 2; kx++) {
            unsigned a[MT][4];
            #pragma unroll
            for (int mt = 0; mt < MT; mt++) {
                int r_ = wm + mt * 16 + (lane >> 2);
                int c_ = kx * 8 + (lane & 3);
                a[mt][0] = As[buf][r_][c_];
                a[mt][1] = As[buf][r_ + 8][c_];
                a[mt][2] = As[buf][r_][c_ + 4];
                a[mt][3] = As[buf][r_ + 8][c_ + 4];
            }
            #pragma unroll
            for (int ct = 0; ct < 4; ct++) {
                unsigned b0 = Bs[buf][kx*8 + (lane & 3)][wn + ct*8 + (lane >> 2)];
                unsigned b1 = Bs[buf][kx*8 + (lane & 3) + 4][wn + ct*8 + (lane >> 2)];
                #pragma unroll
                for (int mt = 0; mt < MT; mt++) {
                    asm volatile(
                        "mma.sync.aligned.m16n8k8.row.col.f32.tf32.tf32.f32 "
                        "{%0,%1,%2,%3}, {%4,%5,%6,%7}, {%8,%9}, {%0,%1,%2,%3};"
                        : "+f"(acc[mt][ct][0]), "+f"(acc[mt][ct][1]),
                          "+f"(acc[mt][ct][2]), "+f"(acc[mt][ct][3])
                        : "r"(a[mt][0]), "r"(a[mt][1]), "r"(a[mt][2]), "r"(a[mt][3]),
                          "r"(b0), "r"(b1));
                }
            }
        }

        if (t + 1 < nt) {
            int nb = buf ^ 1;
            if (BM == 64) {
                *(uint4*)&As[nb][ar][aq*8]     = make_uint4(f2t(fa0.x), f2t(fa0.y), f2t(fa0.z), f2t(fa0.w));
                *(uint4*)&As[nb][ar][aq*8 + 4] = make_uint4(f2t(fa1.x), f2t(fa1.y), f2t(fa1.z), f2t(fa1.w));
            } else {
                *(uint4*)&As[nb][ar][aq*4]     = make_uint4(f2t(fa0.x), f2t(fa0.y), f2t(fa0.z), f2t(fa0.w));
            }
            *(uint4*)&Bs[nb][brw][bc]   = make_uint4(f2t(fb0.x), f2t(fb0.y), f2t(fb0.z), f2t(fb0.w));
            *(uint4*)&Bs[nb][brw+8][bc] = make_uint4(f2t(fb1.x), f2t(fb1.y), f2t(fb1.z), f2t(fb1.w));
        }
        __syncthreads();
    }

    // epilogue
    #pragma unroll
    for (int mt = 0; mt < MT; mt++) {
        #pragma unroll
        for (int rh = 0; rh < 2; rh++) {
            int gm = m0 + wm + mt * 16 + (lane >> 2) + rh * 8;
            float rs = rowscale ? rowscale[gm] : 1.f;
            #pragma unroll
            for (int ct = 0; ct < 4; ct++) {
                int gn = n0 + wn + ct * 8 + (lane & 3) * 2;
                float v0 = acc[mt][ct][rh * 2 + 0];
                float v1 = acc[mt][ct][rh * 2 + 1];
                if (bias) { v0 += bias[gn]; v1 += bias[gn + 1]; }
                v0 *= rs; v1 *= rs;
                long off = (long)gm * ldc + gn;
                if (act == 1) { v0 = tanhf(v0); v1 = tanhf(v1); }
                else if (act == 2) {
                    v0 = 1.f / (1.f + expf(-v0));
                    v1 = 1.f / (1.f + expf(-v1));
                }
                else if (act == 3) {
                    float g0 = 1.f / (1.f + expf(-v0));
                    float g1 = 1.f / (1.f + expf(-v1));
                    v0 = g0 * e1[off]     + (1.f - g0) * e2[off];
                    v1 = g1 * e1[off + 1] + (1.f - g1) * e2[off + 1];
                }
                *(float2*)(Cout + off) = make_float2(v0, v1);
            }
        }
    }
}

// ---------------- fused pairwise scorer (3 j's per thread, fp32) ----------------
__global__ void scorer_kernel(const float* __restrict__ lr,
                              const float* __restrict__ dp,
                              const float* __restrict__ Wo,
                              const float* __restrict__ bo,
                              const int* __restrict__ span_begin,
                              const int* __restrict__ span_end,
                              float* __restrict__ scores,
                              int first)
{
    int i = blockIdx.x, b = blockIdx.y;
    int tid = threadIdx.x;  // 128

    __shared__ float s_l[HP_];
    __shared__ float s_dp[NB_][HP_];
    __shared__ float s_w[L_][HP_];
    __shared__ float s_bo[L_];

    const float* lrow = lr + (long)(b * K_ + i) * LRWP_;
    for (int x = tid; x < HP_; x += 128) s_l[x] = lrow[x];
    for (int x = tid; x < NB_ * HP_; x += 128) s_dp[x / HP_][x % HP_] = dp[x];
    for (int x = tid; x < L_ * HP_; x += 128) {
        int c = x / HP_, h = x % HP_;
        s_w[c][h] = (h < H_) ? Wo[h * L_ + c] : 0.f;
    }
    if (tid < L_) s_bo[tid] = bo[tid];
    __syncthreads();

    int endi = span_end[b * K_ + i];
    const float* rbase = lr + (long)b * K_ * LRWP_ + HP_;

    int j0 = tid, j1 = tid + 128, j2 = tid + 256;

    auto bucket = [&](int j) {
        int d = span_begin[b * K_ + j] - endi;
        int da = d < 0 ? -d : d;
        if (da <= 4) return da;
        int lg = 31 - __clz(da) + 3;
        return lg < (NB_ - 1) ? lg : (NB_ - 1);
    };
    const float* d0 = s_dp[bucket(j0)];
    const float* d1 = s_dp[bucket(j1)];
    const float* d2 = s_dp[bucket(j2)];
    const float* r0 = rbase + (long)j0 * LRWP_;
    const float* r1 = rbase + (long)j1 * LRWP_;
    const float* r2 = rbase + (long)j2 * LRWP_;

    float acc[3][L_];
    #pragma unroll
    for (int c = 0; c < L_; c++) {
        acc[0][c] = s_bo[c]; acc[1][c] = s_bo[c]; acc[2][c] = s_bo[c];
    }

    #pragma unroll 2
    for (int h = 0; h < HP_; h += 4) {
        float4 lv = *(const float4*)(s_l + h);
        float4 rv0 = *(const float4*)(r0 + h);
        float4 rv1 = *(const float4*)(r1 + h);
        float4 rv2 = *(const float4*)(r2 + h);
        float4 dv0 = *(const float4*)(d0 + h);
        float4 dv1 = *(const float4*)(d1 + h);
        float4 dv2 = *(const float4*)(d2 + h);

        float h00 = fmaxf(lv.x + rv0.x + dv0.x, 0.f);
        float h01 = fmaxf(lv.y + rv0.y + dv0.y, 0.f);
        float h02 = fmaxf(lv.z + rv0.z + dv0.z, 0.f);
        float h03 = fmaxf(lv.w + rv0.w + dv0.w, 0.f);
        float h10 = fmaxf(lv.x + rv1.x + dv1.x, 0.f);
        float h11 = fmaxf(lv.y + rv1.y + dv1.y, 0.f);
        float h12 = fmaxf(lv.z + rv1.z + dv1.z, 0.f);
        float h13 = fmaxf(lv.w + rv1.w + dv1.w, 0.f);
        float h20 = fmaxf(lv.x + rv2.x + dv2.x, 0.f);
        float h21 = fmaxf(lv.y + rv2.y + dv2.y, 0.f);
        float h22 = fmaxf(lv.z + rv2.z + dv2.z, 0.f);
        float h23 = fmaxf(lv.w + rv2.w + dv2.w, 0.f);

        #pragma unroll
        for (int c = 0; c < L_; c++) {
            float4 w = *(const float4*)(&s_w[c][h]);
            acc[0][c] += h00 * w.x + h01 * w.y + h02 * w.z + h03 * w.w;
            acc[1][c] += h10 * w.x + h11 * w.y + h12 * w.z + h13 * w.w;
            acc[2][c] += h20 * w.x + h21 * w.y + h22 * w.z + h23 * w.w;
        }
    }

    long rowoff = ((long)(b * K_ + i)) * K_;
    #pragma unroll
    for (int jj = 0; jj < 3; jj++) {
        int j = tid + jj * 128;
        float* out = scores + (rowoff + j) * L_;
        if (first) {
            #pragma unroll
            for (int q = 0; q < 3; q++)
                *(float4*)(out + q * 4) = make_float4(acc[jj][q*4], acc[jj][q*4+1],
                                                      acc[jj][q*4+2], acc[jj][q*4+3]);
        } else {
            #pragma unroll
            for (int q = 0; q < 3; q++) {
                float4 old = *(const float4*)(out + q * 4);
                *(float4*)(out + q * 4) = make_float4(old.x + acc[jj][q*4], old.y + acc[jj][q*4+1],
                                                      old.z + acc[jj][q*4+2], old.w + acc[jj][q*4+3]);
            }
        }
    }
}

// ---------------- probs = sigmoid(max_l scores) * mask ; also transpose ----------------
__global__ void probs_kernel(const float* __restrict__ scores,
                             const float* __restrict__ mask,
                             float* __restrict__ probsAll)
{
    int i = blockIdx.x, b = blockIdx.y;
    for (int j = threadIdx.x; j < K_; j += blockDim.x) {
        const float* s = scores + (((long)(b * K_ + i)) * K_ + j) * L_;
        float m = s[0];
        #pragma unroll
        for (int c = 1; c < L_; c++) m = fmaxf(m, s[c]);
        float p = (1.f / (1.f + expf(-m))) * mask[((long)(b * K_ + i)) * K_ + j];
        probsAll[((long)(b * K_ + i)) * K_ + j] = p;
        probsAll[(long)SZ_P + ((long)(b * K_ + j)) * K_ + i] = p;
    }
}

// ---------------- inverse row sums over probsAll (2*B*K rows) ----------------
__global__ void invsum_kernel(const float* __restrict__ probsAll,
                              float* __restrict__ invAll)
{
    int row = blockIdx.x;
    const float* src = probsAll + (long)row * K_;
    float s = 0.f;
    for (int j = threadIdx.x; j < K_; j += blockDim.x) s += src[j];
    __shared__ float red[4];
    #pragma unroll
    for (int o = 16; o > 0; o >>= 1) s += __shfl_down_sync(0xffffffffu, s, o);
    int wid = threadIdx.x >> 5;
    if ((threadIdx.x & 31) == 0) red[wid] = s;
    __syncthreads();
    if (threadIdx.x == 0) {
        s = red[0] + red[1] + red[2] + red[3];
        invAll[row] = 1.f / (s + 1e-7f);
    }
}

// ---------------- scatter with last-write-wins semantics ----------------
__global__ void scatter_kernel(const float* __restrict__ u,
                               const float* __restrict__ all_span,
                               const int* __restrict__ prune,
                               const int* __restrict__ span_len,
                               float* __restrict__ out_all)
{
    int bk = blockIdx.x;
    int b = bk / K_, k = bk % K_;
    int idx = prune[bk];
    bool last = (k == K_ - 1) || (prune[bk + 1] != idx);
    if (!last) return;
    bool valid = k < span_len[b];
    const float* src = valid ? (u + (long)bk * D_)
                             : (all_span + ((long)b * N_ + idx) * D_);
    float* dst = out_all + ((long)b * N_ + idx) * D_;
    int t = threadIdx.x;
    float4 v = *(const float4*)(src + t * 4);
    *(float4*)(dst + t * 4) = v;
}

// ---------------- host orchestration ----------------
extern "C" void kernel_launch(void* const* d_in, const int* in_sizes, int n_in,
                              void* d_out, int out_size)
{
    const float* span_vecs  = (const float*)d_in[0];
    const float* all_span   = (const float*)d_in[1];
    const int*   span_begin = (const int*)  d_in[2];
    const int*   span_end   = (const int*)  d_in[3];
    const float* mask       = (const float*)d_in[4];
    const int*   prune      = (const int*)  d_in[5];
    const int*   span_len   = (const int*)  d_in[6];
    const float* Wl  = (const float*)d_in[8];
    const float* bl  = (const float*)d_in[9];
    const float* Wr  = (const float*)d_in[10];
    const float* br  = (const float*)d_in[11];
    const float* de  = (const float*)d_in[12];
    const float* Wd  = (const float*)d_in[13];
    const float* bd  = (const float*)d_in[14];
    const float* Wo  = (const float*)d_in[15];
    const float* bo  = (const float*)d_in[16];
    const float* Wff1= (const float*)d_in[17];
    const float* Wff2= (const float*)d_in[18];
    const float* Wg  = (const float*)d_in[19];
    const float* bg  = (const float*)d_in[20];

    float *u, *u2, *lr, *wlr, *blr, *dp, *probsAll, *invAll, *c, *tmp, *ctxt;
    cudaGetSymbolAddress((void**)&u,        g_u);
    cudaGetSymbolAddress((void**)&u2,       g_u2);
    cudaGetSymbolAddress((void**)&lr,       g_lr);
    cudaGetSymbolAddress((void**)&wlr,      g_wlr);
    cudaGetSymbolAddress((void**)&blr,      g_blr);
    cudaGetSymbolAddress((void**)&dp,       g_dp);
    cudaGetSymbolAddress((void**)&probsAll, g_probs);
    cudaGetSymbolAddress((void**)&invAll,   g_inv);
    cudaGetSymbolAddress((void**)&c,        g_c);
    cudaGetSymbolAddress((void**)&tmp,      g_tmp);
    cudaGetSymbolAddress((void**)&ctxt,     g_ctxt);

    float* out_all = (float*)d_out;
    float* out_u   = out_all + (size_t)B_ * N_ * D_;
    float* out_sc  = out_u   + (size_t)B_ * K_ * D_;

    const int M = B_ * K_;  // 768

    cudaMemcpyAsync(u, span_vecs, sizeof(float) * SZ_U, cudaMemcpyDeviceToDevice);
    init_kernel<<<128, 256>>>(de, Wd, bd, Wl, bl, Wr, br, dp, wlr, blr);

    float* ucur = u;
    float* unext = u2;

    // initial l|r projection (BM=32: grid 6x24=144 CTAs) + scorer
    mma_gemm<32><<<dim3(6, 24, 1), 128>>>(ucur, ucur, ucur, wlr, blr, nullptr, nullptr, nullptr,
                                          lr, M, LRWP_, D_, D_, LRWP_, 0, 0, 0, 0, 0, 0);
    scorer_kernel<<<dim3(K_, B_), 128>>>(lr, dp, Wo, bo, span_begin, span_end, out_sc, 1);

    for (int it = 0; it < 2; it++) {
        probs_kernel<<<dim3(K_, B_), 128>>>(out_sc, mask, probsAll);
        invsum_kernel<<<2 * B_ * K_, 128>>>(probsAll, invAll);

        // c[z] = (probsAll[z] @ u[z&1]) * invAll[z]  (grid 16x6x4 = 384 CTAs)
        mma_gemm<64><<<dim3(16, 6, 4), 128>>>(probsAll, probsAll, probsAll, ucur, nullptr, invAll,
                                              nullptr, nullptr, c,
                                              K_, D_, K_, K_, D_,
                                              (long)K_*K_, (long)K_*D_, 1, (long)K_*D_, K_, 0);

        // tmp = tanh([u|c1|c2] @ Wff1)   (grid 16x12 = 192 CTAs)
        mma_gemm<64><<<dim3(16, 12, 1), 128>>>(ucur, c, c + SZ_U, Wff1, nullptr, nullptr,
                                               nullptr, nullptr, tmp,
                                               M, D_, 3 * D_, D_, D_, 0, 0, 0, 0, 0, 1);
        // ctxt = tmp @ Wff2
        mma_gemm<64><<<dim3(16, 12, 1), 128>>>(tmp, tmp, tmp, Wff2, nullptr, nullptr,
                                               nullptr, nullptr, ctxt,
                                               M, D_, D_, D_, D_, 0, 0, 0, 0, 0, 0);
        // unext = g*u + (1-g)*ctxt, g = sigmoid([u|ctxt] @ Wg + bg)
        mma_gemm<64><<<dim3(16, 12, 1), 128>>>(ucur, ctxt, ctxt, Wg, bg, nullptr,
                                               ucur, ctxt, unext,
                                               M, D_, 2 * D_, D_, D_, 0, 0, 0, 0, 0, 3);
        float* t2 = ucur; ucur = unext; unext = t2;

        // re-project + scorer (residual accumulate)
        mma_gemm<32><<<dim3(6, 24, 1), 128>>>(ucur, ucur, ucur, wlr, blr, nullptr, nullptr, nullptr,
                                              lr, M, LRWP_, D_, D_, LRWP_, 0, 0, 0, 0, 0, 0);
        scorer_kernel<<<dim3(K_, B_), 128>>>(lr, dp, Wo, bo, span_begin, span_end, out_sc, 0);
    }

    // outputs: update_all, u, scores (scores already written in place)
    cudaMemcpyAsync(out_all, all_span, sizeof(float) * (size_t)B_ * N_ * D_, cudaMemcpyDeviceToDevice);
    scatter_kernel<<<B_ * K_, 256>>>(ucur, all_span, prune, span_len, out_all);
    cudaMemcpyAsync(out_u, ucur, sizeof(float) * SZ_U, cudaMemcpyDeviceToDevice);
}

// round 5
// speedup vs baseline: 3.3524x; 1.3511x over previous
#include <cuda_runtime.h>
#include <math.h>

// ---------------- problem constants ----------------
#define B_    2
#define K_    384
#define N_    4096
#define D_    1024
#define H_    150
#define HP_   152     // padded H
#define LRWP_ 384     // l|r concatenated row width, padded
#define L_    12
#define NB_   10
#define DE_   20

#define SZ_U   (B_*K_*D_)       // 786432
#define SZ_P   (B_*K_*K_)       // 294912
#define SZ_S   (B_*K_)          // 768

// ---------------- device scratch (static, no allocs) ----------------
__device__ float g_u[SZ_U];        // fp32 u (ping)
__device__ float g_u2[SZ_U];       // fp32 u (pong)
__device__ float g_ut[SZ_U];       // tf32-clean u (ping)
__device__ float g_ut2[SZ_U];      // tf32-clean u (pong)
__device__ float g_lr[B_*K_*LRWP_];
__device__ float g_wlr[D_*LRWP_];  // tf32-clean
__device__ float g_blr[LRWP_];
__device__ float g_dp[NB_*HP_];
__device__ float g_probs[2*SZ_P];  // tf32-clean [probs b0,b1 | probsT b0,b1]
__device__ float g_inv[2*SZ_S];
__device__ float g_c[2*SZ_U];      // tf32-clean [c1 b0,b1 | c2 b0,b1]
__device__ float g_tmp[SZ_U];      // tf32-clean
__device__ float g_ctxt[SZ_U];     // tf32-clean
__device__ float g_wff1t[3*D_*D_]; // tf32-clean weights
__device__ float g_wff2t[D_*D_];
__device__ float g_wgt[2*D_*D_];

__device__ __forceinline__ unsigned f2t(float x) {
    unsigned r;
    asm("cvt.rna.tf32.f32 %0, %1;" : "=r"(r) : "f"(x));
    return r;
}
__device__ __forceinline__ float rna(float x) { return __uint_as_float(f2t(x)); }

__device__ __forceinline__ void cpa16(void* s, const void* g) {
    unsigned sa = (unsigned)__cvta_generic_to_shared(s);
    asm volatile("cp.async.cg.shared.global [%0], [%1], 16;" :: "r"(sa), "l"(g));
}
__device__ __forceinline__ void cp_commit() { asm volatile("cp.async.commit_group;"); }
template<int Nw>
__device__ __forceinline__ void cp_wait() { asm volatile("cp.async.wait_group %0;" :: "n"(Nw)); }

// ---------------- weight/input tf32 conversion (once per launch) ----------------
__global__ void convert_kernel(const float* __restrict__ Wff1,
                               const float* __restrict__ Wff2,
                               const float* __restrict__ Wg,
                               const float* __restrict__ span_vecs,
                               float* __restrict__ wff1t,
                               float* __restrict__ wff2t,
                               float* __restrict__ wgt,
                               float* __restrict__ u,
                               float* __restrict__ ut)
{
    int tid = blockIdx.x * blockDim.x + threadIdx.x;
    int nthr = gridDim.x * blockDim.x;
    for (int i = tid; i < 3*D_*D_; i += nthr) wff1t[i] = rna(Wff1[i]);
    for (int i = tid; i < D_*D_;   i += nthr) wff2t[i] = rna(Wff2[i]);
    for (int i = tid; i < 2*D_*D_; i += nthr) wgt[i]   = rna(Wg[i]);
    for (int i = tid; i < SZ_U; i += nthr) {
        float v = span_vecs[i];
        u[i] = v;
        ut[i] = rna(v);
    }
}

// ---------------- init: dp table + W_lr / b_lr concat (tf32-clean) ----------------
__global__ void init_kernel(const float* __restrict__ dist_emb,
                            const float* __restrict__ Wd,
                            const float* __restrict__ bd,
                            const float* __restrict__ Wl,
                            const float* __restrict__ bl,
                            const float* __restrict__ Wr,
                            const float* __restrict__ br,
                            float* __restrict__ dp,
                            float* __restrict__ wlr,
                            float* __restrict__ blr)
{
    int tid = blockIdx.x * blockDim.x + threadIdx.x;
    int nthr = gridDim.x * blockDim.x;
    for (int idx = tid; idx < NB_*HP_; idx += nthr) {
        int n = idx / HP_, h = idx % HP_;
        float v = 0.f;
        if (h < H_) {
            v = bd[h];
            #pragma unroll
            for (int t = 0; t < DE_; t++)
                v += dist_emb[n * DE_ + t] * Wd[t * H_ + h];
        }
        dp[idx] = v;
    }
    for (int idx = tid; idx < D_*LRWP_; idx += nthr) {
        int k = idx / LRWP_, c = idx % LRWP_;
        float v = 0.f;
        if (c < H_) v = Wl[k * H_ + c];
        else if (c >= HP_ && c < HP_ + H_) v = Wr[k * H_ + (c - HP_)];
        wlr[idx] = rna(v);
    }
    for (int c = tid; c < LRWP_; c += nthr) {
        float v = 0.f;
        if (c < H_) v = bl[c];
        else if (c >= HP_ && c < HP_ + H_) v = br[c - HP_];
        blr[c] = v;
    }
}

// ---------------- tf32 tensor-core GEMM, cp.async 2-stage, K-step 32 ----------------
// All operands must be tf32-clean fp32 (low mantissa bits zero).
// 128 threads, 4 warps (2x2), warp tile (BM/2) x 32.
// Requires: M % BM == 0, N % 64 == 0, K % 32 == 0.
// A segmented along K in 1024-wide chunks (a0,a1,a2), each row stride lda.
// C = act( rowscale * (A @ W + bias) )
// act: 0=none, 1=tanh, 2=sigmoid, 3=gate: g=sigmoid(v); C = g*e1 + (1-g)*e2
// roundOut: write rna-rounded values. Ct: optional tf32-clean secondary output.
template<int BM>
__global__ void __launch_bounds__(128, 2)
mma_gemm(const float* __restrict__ a0,
         const float* __restrict__ a1,
         const float* __restrict__ a2,
         const float* __restrict__ W,
         const float* __restrict__ bias,
         const float* __restrict__ rowscale,
         const float* __restrict__ e1,
         const float* __restrict__ e2,
         float* __restrict__ Cout,
         float* __restrict__ Ct,
         int M, int N, int K, int lda, int ldc,
         long sA, long sW, int bzmask, long sC, int sRS,
         int act, int roundOut)
{
    constexpr int MT = BM / 32;
    constexpr int ACH = (BM == 64) ? 4 : 2;   // A cp.async chunks per thread
    __shared__ unsigned As[2][BM][36];        // stride 36 -> conflict-free frags
    __shared__ unsigned Bs[2][32][72];        // stride 72 -> conflict-free frags

    int z = blockIdx.z;
    a0 += (long)z * sA;
    W  += (long)(z & bzmask) * sW;
    Cout += (long)z * sC;
    if (rowscale) rowscale += (long)z * sRS;

    int tid = threadIdx.x;
    int warp = tid >> 5, lane = tid & 31;
    int m0 = blockIdx.y * BM, n0 = blockIdx.x * 64;
    int wm = (warp >> 1) * (BM / 2), wn = (warp & 1) * 32;

    auto issue = [&](int k0, int buf) {
        int seg = k0 >> 10, col = k0 & 1023;
        const float* ap = (seg == 0) ? a0 : (seg == 1) ? a1 : a2;
        #pragma unroll
        for (int i = 0; i < ACH; i++) {
            int id = tid + i * 128;
            int row = id >> 3, c16 = (id & 7) * 4;
            cpa16(&As[buf][row][c16], ap + (long)(m0 + row) * lda + col + c16);
        }
        #pragma unroll
        for (int i = 0; i < 4; i++) {
            int id = tid + i * 128;
            int kr = id >> 4, c16 = (id & 15) * 4;
            cpa16(&Bs[buf][kr][c16], W + (long)(k0 + kr) * N + n0 + c16);
        }
        cp_commit();
    };

    int nt = K >> 5;
    issue(0, 0);

    float acc[MT][4][4];
    #pragma unroll
    for (int i = 0; i < MT; i++)
        #pragma unroll
        for (int j = 0; j < 4; j++)
            #pragma unroll
            for (int q = 0; q < 4; q++) acc[i][j][q] = 0.f;

    for (int t = 0; t < nt; t++) {
        int buf = t & 1;
        if (t + 1 < nt) {
            issue((t + 1) << 5, buf ^ 1);
            cp_wait<1>();
        } else {
            cp_wait<0>();
        }
        __syncthreads();

        #pragma unroll
        for (int kx = 0; kx < 4; kx++) {
            unsigned a[MT][4];
            #pragma unroll
            for (int mt = 0; mt < MT; mt++) {
                int r_ = wm + mt * 16 + (lane >> 2);
                int c_ = kx * 8 + (lane & 3);
                a[mt][0] = As[buf][r_][c_];
                a[mt][1] = As[buf][r_ + 8][c_];
                a[mt][2] = As[buf][r_][c_ + 4];
                a[mt][3] = As[buf][r_ + 8][c_ + 4];
            }
            #pragma unroll
            for (int ct = 0; ct < 4; ct++) {
                unsigned b0 = Bs[buf][kx*8 + (lane & 3)][wn + ct*8 + (lane >> 2)];
                unsigned b1 = Bs[buf][kx*8 + (lane & 3) + 4][wn + ct*8 + (lane >> 2)];
                #pragma unroll
                for (int mt = 0; mt < MT; mt++) {
                    asm volatile(
                        "mma.sync.aligned.m16n8k8.row.col.f32.tf32.tf32.f32 "
                        "{%0,%1,%2,%3}, {%4,%5,%6,%7}, {%8,%9}, {%0,%1,%2,%3};"
                        : "+f"(acc[mt][ct][0]), "+f"(acc[mt][ct][1]),
                          "+f"(acc[mt][ct][2]), "+f"(acc[mt][ct][3])
                        : "r"(a[mt][0]), "r"(a[mt][1]), "r"(a[mt][2]), "r"(a[mt][3]),
                          "r"(b0), "r"(b1));
                }
            }
        }
        __syncthreads();
    }

    // epilogue
    #pragma unroll
    for (int mt = 0; mt < MT; mt++) {
        #pragma unroll
        for (int rh = 0; rh < 2; rh++) {
            int gm = m0 + wm + mt * 16 + (lane >> 2) + rh * 8;
            float rs = rowscale ? rowscale[gm] : 1.f;
            #pragma unroll
            for (int ct = 0; ct < 4; ct++) {
                int gn = n0 + wn + ct * 8 + (lane & 3) * 2;
                float v0 = acc[mt][ct][rh * 2 + 0];
                float v1 = acc[mt][ct][rh * 2 + 1];
                if (bias) { v0 += bias[gn]; v1 += bias[gn + 1]; }
                v0 *= rs; v1 *= rs;
                long off = (long)gm * ldc + gn;
                if (act == 1) { v0 = tanhf(v0); v1 = tanhf(v1); }
                else if (act == 2) {
                    v0 = 1.f / (1.f + expf(-v0));
                    v1 = 1.f / (1.f + expf(-v1));
                }
                else if (act == 3) {
                    float g0 = 1.f / (1.f + expf(-v0));
                    float g1 = 1.f / (1.f + expf(-v1));
                    v0 = g0 * e1[off]     + (1.f - g0) * e2[off];
                    v1 = g1 * e1[off + 1] + (1.f - g1) * e2[off + 1];
                }
                if (roundOut) { v0 = rna(v0); v1 = rna(v1); }
                *(float2*)(Cout + off) = make_float2(v0, v1);
                if (Ct) *(float2*)(Ct + off) = make_float2(rna(v0), rna(v1));
            }
        }
    }
}

// ---------------- fused pairwise scorer (3 j's per thread, fp32) ----------------
__global__ void scorer_kernel(const float* __restrict__ lr,
                              const float* __restrict__ dp,
                              const float* __restrict__ Wo,
                              const float* __restrict__ bo,
                              const int* __restrict__ span_begin,
                              const int* __restrict__ span_end,
                              float* __restrict__ scores,
                              int first)
{
    int i = blockIdx.x, b = blockIdx.y;
    int tid = threadIdx.x;  // 128

    __shared__ float s_l[HP_];
    __shared__ float s_dp[NB_][HP_];
    __shared__ float s_w[L_][HP_];
    __shared__ float s_bo[L_];

    const float* lrow = lr + (long)(b * K_ + i) * LRWP_;
    for (int x = tid; x < HP_; x += 128) s_l[x] = lrow[x];
    for (int x = tid; x < NB_ * HP_; x += 128) s_dp[x / HP_][x % HP_] = dp[x];
    for (int x = tid; x < L_ * HP_; x += 128) {
        int c = x / HP_, h = x % HP_;
        s_w[c][h] = (h < H_) ? Wo[h * L_ + c] : 0.f;
    }
    if (tid < L_) s_bo[tid] = bo[tid];
    __syncthreads();

    int endi = span_end[b * K_ + i];
    const float* rbase = lr + (long)b * K_ * LRWP_ + HP_;

    int j0 = tid, j1 = tid + 128, j2 = tid + 256;

    auto bucket = [&](int j) {
        int d = span_begin[b * K_ + j] - endi;
        int da = d < 0 ? -d : d;
        if (da <= 4) return da;
        int lg = 31 - __clz(da) + 3;
        return lg < (NB_ - 1) ? lg : (NB_ - 1);
    };
    const float* d0 = s_dp[bucket(j0)];
    const float* d1 = s_dp[bucket(j1)];
    const float* d2 = s_dp[bucket(j2)];
    const float* r0 = rbase + (long)j0 * LRWP_;
    const float* r1 = rbase + (long)j1 * LRWP_;
    const float* r2 = rbase + (long)j2 * LRWP_;

    float acc[3][L_];
    #pragma unroll
    for (int c = 0; c < L_; c++) {
        acc[0][c] = s_bo[c]; acc[1][c] = s_bo[c]; acc[2][c] = s_bo[c];
    }

    #pragma unroll 2
    for (int h = 0; h < HP_; h += 4) {
        float4 lv = *(const float4*)(s_l + h);
        float4 rv0 = *(const float4*)(r0 + h);
        float4 rv1 = *(const float4*)(r1 + h);
        float4 rv2 = *(const float4*)(r2 + h);
        float4 dv0 = *(const float4*)(d0 + h);
        float4 dv1 = *(const float4*)(d1 + h);
        float4 dv2 = *(const float4*)(d2 + h);

        float h00 = fmaxf(lv.x + rv0.x + dv0.x, 0.f);
        float h01 = fmaxf(lv.y + rv0.y + dv0.y, 0.f);
        float h02 = fmaxf(lv.z + rv0.z + dv0.z, 0.f);
        float h03 = fmaxf(lv.w + rv0.w + dv0.w, 0.f);
        float h10 = fmaxf(lv.x + rv1.x + dv1.x, 0.f);
        float h11 = fmaxf(lv.y + rv1.y + dv1.y, 0.f);
        float h12 = fmaxf(lv.z + rv1.z + dv1.z, 0.f);
        float h13 = fmaxf(lv.w + rv1.w + dv1.w, 0.f);
        float h20 = fmaxf(lv.x + rv2.x + dv2.x, 0.f);
        float h21 = fmaxf(lv.y + rv2.y + dv2.y, 0.f);
        float h22 = fmaxf(lv.z + rv2.z + dv2.z, 0.f);
        float h23 = fmaxf(lv.w + rv2.w + dv2.w, 0.f);

        #pragma unroll
        for (int c = 0; c < L_; c++) {
            float4 w = *(const float4*)(&s_w[c][h]);
            acc[0][c] += h00 * w.x + h01 * w.y + h02 * w.z + h03 * w.w;
            acc[1][c] += h10 * w.x + h11 * w.y + h12 * w.z + h13 * w.w;
            acc[2][c] += h20 * w.x + h21 * w.y + h22 * w.z + h23 * w.w;
        }
    }

    long rowoff = ((long)(b * K_ + i)) * K_;
    #pragma unroll
    for (int jj = 0; jj < 3; jj++) {
        int j = tid + jj * 128;
        float* out = scores + (rowoff + j) * L_;
        if (first) {
            #pragma unroll
            for (int q = 0; q < 3; q++)
                *(float4*)(out + q * 4) = make_float4(acc[jj][q*4], acc[jj][q*4+1],
                                                      acc[jj][q*4+2], acc[jj][q*4+3]);
        } else {
            #pragma unroll
            for (int q = 0; q < 3; q++) {
                float4 old = *(const float4*)(out + q * 4);
                *(float4*)(out + q * 4) = make_float4(old.x + acc[jj][q*4], old.y + acc[jj][q*4+1],
                                                      old.z + acc[jj][q*4+2], old.w + acc[jj][q*4+3]);
            }
        }
    }
}

// ---------------- probs = sigmoid(max_l scores) * mask (tf32-clean) + transpose ----------------
__global__ void probs_kernel(const float* __restrict__ scores,
                             const float* __restrict__ mask,
                             float* __restrict__ probsAll)
{
    int i = blockIdx.x, b = blockIdx.y;
    for (int j = threadIdx.x; j < K_; j += blockDim.x) {
        const float* s = scores + (((long)(b * K_ + i)) * K_ + j) * L_;
        float m = s[0];
        #pragma unroll
        for (int c = 1; c < L_; c++) m = fmaxf(m, s[c]);
        float p = rna((1.f / (1.f + expf(-m))) * mask[((long)(b * K_ + i)) * K_ + j]);
        probsAll[((long)(b * K_ + i)) * K_ + j] = p;
        probsAll[(long)SZ_P + ((long)(b * K_ + j)) * K_ + i] = p;
    }
}

// ---------------- inverse row sums over probsAll (2*B*K rows) ----------------
__global__ void invsum_kernel(const float* __restrict__ probsAll,
                              float* __restrict__ invAll)
{
    int row = blockIdx.x;
    const float* src = probsAll + (long)row * K_;
    float s = 0.f;
    for (int j = threadIdx.x; j < K_; j += blockDim.x) s += src[j];
    __shared__ float red[4];
    #pragma unroll
    for (int o = 16; o > 0; o >>= 1) s += __shfl_down_sync(0xffffffffu, s, o);
    int wid = threadIdx.x >> 5;
    if ((threadIdx.x & 31) == 0) red[wid] = s;
    __syncthreads();
    if (threadIdx.x == 0) {
        s = red[0] + red[1] + red[2] + red[3];
        invAll[row] = 1.f / (s + 1e-7f);
    }
}

// ---------------- scatter with last-write-wins semantics ----------------
__global__ void scatter_kernel(const float* __restrict__ u,
                               const float* __restrict__ all_span,
                               const int* __restrict__ prune,
                               const int* __restrict__ span_len,
                               float* __restrict__ out_all)
{
    int bk = blockIdx.x;
    int b = bk / K_, k = bk % K_;
    int idx = prune[bk];
    bool last = (k == K_ - 1) || (prune[bk + 1] != idx);
    if (!last) return;
    bool valid = k < span_len[b];
    const float* src = valid ? (u + (long)bk * D_)
                             : (all_span + ((long)b * N_ + idx) * D_);
    float* dst = out_all + ((long)b * N_ + idx) * D_;
    int t = threadIdx.x;
    float4 v = *(const float4*)(src + t * 4);
    *(float4*)(dst + t * 4) = v;
}

// ---------------- host orchestration ----------------
extern "C" void kernel_launch(void* const* d_in, const int* in_sizes, int n_in,
                              void* d_out, int out_size)
{
    const float* span_vecs  = (const float*)d_in[0];
    const float* all_span   = (const float*)d_in[1];
    const int*   span_begin = (const int*)  d_in[2];
    const int*   span_end   = (const int*)  d_in[3];
    const float* mask       = (const float*)d_in[4];
    const int*   prune      = (const int*)  d_in[5];
    const int*   span_len   = (const int*)  d_in[6];
    const float* Wl  = (const float*)d_in[8];
    const float* bl  = (const float*)d_in[9];
    const float* Wr  = (const float*)d_in[10];
    const float* br  = (const float*)d_in[11];
    const float* de  = (const float*)d_in[12];
    const float* Wd  = (const float*)d_in[13];
    const float* bd  = (const float*)d_in[14];
    const float* Wo  = (const float*)d_in[15];
    const float* bo  = (const float*)d_in[16];
    const float* Wff1= (const float*)d_in[17];
    const float* Wff2= (const float*)d_in[18];
    const float* Wg  = (const float*)d_in[19];
    const float* bg  = (const float*)d_in[20];

    float *u, *u2, *ut, *ut2, *lr, *wlr, *blr, *dp, *probsAll, *invAll, *c, *tmp, *ctxt;
    float *wff1t, *wff2t, *wgt;
    cudaGetSymbolAddress((void**)&u,        g_u);
    cudaGetSymbolAddress((void**)&u2,       g_u2);
    cudaGetSymbolAddress((void**)&ut,       g_ut);
    cudaGetSymbolAddress((void**)&ut2,      g_ut2);
    cudaGetSymbolAddress((void**)&lr,       g_lr);
    cudaGetSymbolAddress((void**)&wlr,      g_wlr);
    cudaGetSymbolAddress((void**)&blr,      g_blr);
    cudaGetSymbolAddress((void**)&dp,       g_dp);
    cudaGetSymbolAddress((void**)&probsAll, g_probs);
    cudaGetSymbolAddress((void**)&invAll,   g_inv);
    cudaGetSymbolAddress((void**)&c,        g_c);
    cudaGetSymbolAddress((void**)&tmp,      g_tmp);
    cudaGetSymbolAddress((void**)&ctxt,     g_ctxt);
    cudaGetSymbolAddress((void**)&wff1t,    g_wff1t);
    cudaGetSymbolAddress((void**)&wff2t,    g_wff2t);
    cudaGetSymbolAddress((void**)&wgt,      g_wgt);

    float* out_all = (float*)d_out;
    float* out_u   = out_all + (size_t)B_ * N_ * D_;
    float* out_sc  = out_u   + (size_t)B_ * K_ * D_;

    const int M = B_ * K_;  // 768

    convert_kernel<<<148, 256>>>(Wff1, Wff2, Wg, span_vecs, wff1t, wff2t, wgt, u, ut);
    init_kernel<<<128, 256>>>(de, Wd, bd, Wl, bl, Wr, br, dp, wlr, blr);

    float *ucur = u,  *unext = u2;
    float *utcur = ut, *utnext = ut2;

    // initial l|r projection + scorer
    mma_gemm<32><<<dim3(6, 24, 1), 128>>>(utcur, utcur, utcur, wlr, blr, nullptr, nullptr, nullptr,
                                          lr, nullptr, M, LRWP_, D_, D_, LRWP_, 0, 0, 0, 0, 0, 0, 0);
    scorer_kernel<<<dim3(K_, B_), 128>>>(lr, dp, Wo, bo, span_begin, span_end, out_sc, 1);

    for (int it = 0; it < 2; it++) {
        probs_kernel<<<dim3(K_, B_), 128>>>(out_sc, mask, probsAll);
        invsum_kernel<<<2 * B_ * K_, 128>>>(probsAll, invAll);

        // c[z] = (probsAll[z] @ ut[z&1]) * invAll[z]  (tf32-clean out)
        mma_gemm<64><<<dim3(16, 6, 4), 128>>>(probsAll, probsAll, probsAll, utcur, nullptr, invAll,
                                              nullptr, nullptr, c, nullptr,
                                              K_, D_, K_, K_, D_,
                                              (long)K_*K_, (long)K_*D_, 1, (long)K_*D_, K_, 0, 1);

        // tmp = tanh([ut|c1|c2] @ Wff1)  (tf32-clean out)
        mma_gemm<64><<<dim3(16, 12, 1), 128>>>(utcur, c, c + SZ_U, wff1t, nullptr, nullptr,
                                               nullptr, nullptr, tmp, nullptr,
                                               M, D_, 3 * D_, D_, D_, 0, 0, 0, 0, 0, 1, 1);
        // ctxt = tmp @ Wff2  (tf32-clean out)
        mma_gemm<64><<<dim3(16, 12, 1), 128>>>(tmp, tmp, tmp, wff2t, nullptr, nullptr,
                                               nullptr, nullptr, ctxt, nullptr,
                                               M, D_, D_, D_, D_, 0, 0, 0, 0, 0, 0, 1);
        // unext = g*u + (1-g)*ctxt (fp32), utnext = rna(unext)
        mma_gemm<64><<<dim3(16, 12, 1), 128>>>(utcur, ctxt, ctxt, wgt, bg, nullptr,
                                               ucur, ctxt, unext, utnext,
                                               M, D_, 2 * D_, D_, D_, 0, 0, 0, 0, 0, 3, 0);
        float* s1 = ucur; ucur = unext; unext = s1;
        float* s2 = utcur; utcur = utnext; utnext = s2;

        // re-project + scorer (residual accumulate)
        mma_gemm<32><<<dim3(6, 24, 1), 128>>>(utcur, utcur, utcur, wlr, blr, nullptr, nullptr, nullptr,
                                              lr, nullptr, M, LRWP_, D_, D_, LRWP_, 0, 0, 0, 0, 0, 0, 0);
        scorer_kernel<<<dim3(K_, B_), 128>>>(lr, dp, Wo, bo, span_begin, span_end, out_sc, 0);
    }

    // outputs: update_all, u, scores (scores already written in place)
    cudaMemcpyAsync(out_all, all_span, sizeof(float) * (size_t)B_ * N_ * D_, cudaMemcpyDeviceToDevice);
    scatter_kernel<<<B_ * K_, 256>>>(ucur, all_span, prune, span_len, out_all);
    cudaMemcpyAsync(out_u, ucur, sizeof(float) * SZ_U, cudaMemcpyDeviceToDevice);
}

// round 6
// speedup vs baseline: 3.4227x; 1.0210x over previous
#include <cuda_runtime.h>
#include <math.h>

// ---------------- problem constants ----------------
#define B_    2
#define K_    384
#define N_    4096
#define D_    1024
#define H_    150
#define HP_   152     // padded H
#define LRWP_ 384     // l|r concatenated row width, padded
#define L_    12
#define NB_   10
#define DE_   20

#define SZ_U   (B_*K_*D_)       // 786432
#define SZ_P   (B_*K_*K_)       // 294912
#define SZ_S   (B_*K_)          // 768

// ---------------- device scratch (static, no allocs) ----------------
__device__ float g_u[SZ_U];        // fp32 u (ping)
__device__ float g_u2[SZ_U];       // fp32 u (pong)
__device__ float g_ut[SZ_U];       // tf32-clean u (ping)
__device__ float g_ut2[SZ_U];      // tf32-clean u (pong)
__device__ float g_lr[B_*K_*LRWP_];
__device__ float g_wlr[D_*LRWP_];  // tf32-clean
__device__ float g_blr[LRWP_];
__device__ float g_dp[NB_*HP_];
__device__ float g_probs[2*SZ_P];  // tf32-clean [probs b0,b1 | probsT b0,b1]
__device__ float g_inv[2*SZ_S];
__device__ float g_c[2*SZ_U];      // tf32-clean [c1 b0,b1 | c2 b0,b1]
__device__ float g_tmp[SZ_U];      // tf32-clean
__device__ float g_ctxt[SZ_U];     // tf32-clean
__device__ float g_wff1t[3*D_*D_]; // tf32-clean weights
__device__ float g_wff2t[D_*D_];
__device__ float g_wgt[2*D_*D_];

__device__ __forceinline__ unsigned f2t(float x) {
    unsigned r;
    asm("cvt.rna.tf32.f32 %0, %1;" : "=r"(r) : "f"(x));
    return r;
}
__device__ __forceinline__ float rna(float x) { return __uint_as_float(f2t(x)); }

__device__ __forceinline__ void cpa16(void* s, const void* g) {
    unsigned sa = (unsigned)__cvta_generic_to_shared(s);
    asm volatile("cp.async.cg.shared.global [%0], [%1], 16;" :: "r"(sa), "l"(g));
}
__device__ __forceinline__ void cp_commit() { asm volatile("cp.async.commit_group;"); }
template<int Nw>
__device__ __forceinline__ void cp_wait() { asm volatile("cp.async.wait_group %0;" :: "n"(Nw)); }

// ---------------- weight/input tf32 conversion (once per launch) ----------------
__global__ void convert_kernel(const float* __restrict__ Wff1,
                               const float* __restrict__ Wff2,
                               const float* __restrict__ Wg,
                               const float* __restrict__ span_vecs,
                               float* __restrict__ wff1t,
                               float* __restrict__ wff2t,
                               float* __restrict__ wgt,
                               float* __restrict__ u,
                               float* __restrict__ ut)
{
    int tid = blockIdx.x * blockDim.x + threadIdx.x;
    int nthr = gridDim.x * blockDim.x;
    for (int i = tid; i < 3*D_*D_; i += nthr) wff1t[i] = rna(Wff1[i]);
    for (int i = tid; i < D_*D_;   i += nthr) wff2t[i] = rna(Wff2[i]);
    for (int i = tid; i < 2*D_*D_; i += nthr) wgt[i]   = rna(Wg[i]);
    for (int i = tid; i < SZ_U; i += nthr) {
        float v = span_vecs[i];
        u[i] = v;
        ut[i] = rna(v);
    }
}

// ---------------- init: dp table + W_lr / b_lr concat (tf32-clean) ----------------
__global__ void init_kernel(const float* __restrict__ dist_emb,
                            const float* __restrict__ Wd,
                            const float* __restrict__ bd,
                            const float* __restrict__ Wl,
                            const float* __restrict__ bl,
                            const float* __restrict__ Wr,
                            const float* __restrict__ br,
                            float* __restrict__ dp,
                            float* __restrict__ wlr,
                            float* __restrict__ blr)
{
    int tid = blockIdx.x * blockDim.x + threadIdx.x;
    int nthr = gridDim.x * blockDim.x;
    for (int idx = tid; idx < NB_*HP_; idx += nthr) {
        int n = idx / HP_, h = idx % HP_;
        float v = 0.f;
        if (h < H_) {
            v = bd[h];
            #pragma unroll
            for (int t = 0; t < DE_; t++)
                v += dist_emb[n * DE_ + t] * Wd[t * H_ + h];
        }
        dp[idx] = v;
    }
    for (int idx = tid; idx < D_*LRWP_; idx += nthr) {
        int k = idx / LRWP_, c = idx % LRWP_;
        float v = 0.f;
        if (c < H_) v = Wl[k * H_ + c];
        else if (c >= HP_ && c < HP_ + H_) v = Wr[k * H_ + (c - HP_)];
        wlr[idx] = rna(v);
    }
    for (int c = tid; c < LRWP_; c += nthr) {
        float v = 0.f;
        if (c < H_) v = bl[c];
        else if (c >= HP_ && c < HP_ + H_) v = br[c - HP_];
        blr[c] = v;
    }
}

// ---------------- tf32 tensor-core GEMM, cp.async 3-stage, single sync/tile ----------------
// All operands tf32-clean fp32. 128 threads, 4 warps (2x2), warp tile (BM/2) x 32.
// Requires: M % BM == 0, N % 64 == 0, K % 32 == 0.
// A segmented along K in 1024-wide chunks (a0,a1,a2), each row stride lda.
// C = act( rowscale * (A @ W + bias) ); act 3 = gate. Ct: optional tf32-clean copy.
#define ASTRIDE 36
#define BSTRIDE 72
template<int BM>
__global__ void __launch_bounds__(128, 2)
mma_gemm(const float* __restrict__ a0,
         const float* __restrict__ a1,
         const float* __restrict__ a2,
         const float* __restrict__ W,
         const float* __restrict__ bias,
         const float* __restrict__ rowscale,
         const float* __restrict__ e1,
         const float* __restrict__ e2,
         float* __restrict__ Cout,
         float* __restrict__ Ct,
         int M, int N, int K, int lda, int ldc,
         long sA, long sW, int bzmask, long sC, int sRS,
         int act, int roundOut)
{
    constexpr int MT = BM / 32;
    constexpr int ACH = (BM == 64) ? 4 : 2;
    constexpr int ASZ = BM * ASTRIDE;
    constexpr int BSZ = 32 * BSTRIDE;
    extern __shared__ unsigned dsm[];
    unsigned* Abase = dsm;             // 3 stages of [BM][ASTRIDE]
    unsigned* Bbase = dsm + 3 * ASZ;   // 3 stages of [32][BSTRIDE]

    int z = blockIdx.z;
    a0 += (long)z * sA;
    W  += (long)(z & bzmask) * sW;
    Cout += (long)z * sC;
    if (rowscale) rowscale += (long)z * sRS;

    int tid = threadIdx.x;
    int warp = tid >> 5, lane = tid & 31;
    int m0 = blockIdx.y * BM, n0 = blockIdx.x * 64;
    int wm = (warp >> 1) * (BM / 2), wn = (warp & 1) * 32;

    auto issue = [&](int k0, int stage) {
        unsigned* As = Abase + stage * ASZ;
        unsigned* Bs = Bbase + stage * BSZ;
        int seg = k0 >> 10, col = k0 & 1023;
        const float* ap = (seg == 0) ? a0 : (seg == 1) ? a1 : a2;
        #pragma unroll
        for (int i = 0; i < ACH; i++) {
            int id = tid + i * 128;
            int row = id >> 3, c16 = (id & 7) * 4;
            cpa16(As + row * ASTRIDE + c16, ap + (long)(m0 + row) * lda + col + c16);
        }
        #pragma unroll
        for (int i = 0; i < 4; i++) {
            int id = tid + i * 128;
            int kr = id >> 4, c16 = (id & 15) * 4;
            cpa16(Bs + kr * BSTRIDE + c16, W + (long)(k0 + kr) * N + n0 + c16);
        }
        cp_commit();
    };

    int nt = K >> 5;  // nt >= 2 for all our shapes
    issue(0, 0);
    issue(32, 1);

    float acc[MT][4][4];
    #pragma unroll
    for (int i = 0; i < MT; i++)
        #pragma unroll
        for (int j = 0; j < 4; j++)
            #pragma unroll
            for (int q = 0; q < 4; q++) acc[i][j][q] = 0.f;

    int stage = 0;
    for (int t = 0; t < nt; t++) {
        if (t == nt - 1) cp_wait<0>(); else cp_wait<1>();
        __syncthreads();
        if (t + 2 < nt) issue((t + 2) << 5, (stage + 2) % 3);

        unsigned* As = Abase + stage * ASZ;
        unsigned* Bs = Bbase + stage * BSZ;

        #pragma unroll
        for (int kx = 0; kx < 4; kx++) {
            unsigned a[MT][4];
            #pragma unroll
            for (int mt = 0; mt < MT; mt++) {
                int r_ = wm + mt * 16 + (lane >> 2);
                int c_ = kx * 8 + (lane & 3);
                a[mt][0] = As[r_ * ASTRIDE + c_];
                a[mt][1] = As[(r_ + 8) * ASTRIDE + c_];
                a[mt][2] = As[r_ * ASTRIDE + c_ + 4];
                a[mt][3] = As[(r_ + 8) * ASTRIDE + c_ + 4];
            }
            #pragma unroll
            for (int ct = 0; ct < 4; ct++) {
                unsigned b0 = Bs[(kx*8 + (lane & 3)) * BSTRIDE + wn + ct*8 + (lane >> 2)];
                unsigned b1 = Bs[(kx*8 + (lane & 3) + 4) * BSTRIDE + wn + ct*8 + (lane >> 2)];
                #pragma unroll
                for (int mt = 0; mt < MT; mt++) {
                    asm volatile(
                        "mma.sync.aligned.m16n8k8.row.col.f32.tf32.tf32.f32 "
                        "{%0,%1,%2,%3}, {%4,%5,%6,%7}, {%8,%9}, {%0,%1,%2,%3};"
                        : "+f"(acc[mt][ct][0]), "+f"(acc[mt][ct][1]),
                          "+f"(acc[mt][ct][2]), "+f"(acc[mt][ct][3])
                        : "r"(a[mt][0]), "r"(a[mt][1]), "r"(a[mt][2]), "r"(a[mt][3]),
                          "r"(b0), "r"(b1));
                }
            }
        }
        stage = (stage + 1) % 3;
    }

    // epilogue
    #pragma unroll
    for (int mt = 0; mt < MT; mt++) {
        #pragma unroll
        for (int rh = 0; rh < 2; rh++) {
            int gm = m0 + wm + mt * 16 + (lane >> 2) + rh * 8;
            float rs = rowscale ? rowscale[gm] : 1.f;
            #pragma unroll
            for (int ct = 0; ct < 4; ct++) {
                int gn = n0 + wn + ct * 8 + (lane & 3) * 2;
                float v0 = acc[mt][ct][rh * 2 + 0];
                float v1 = acc[mt][ct][rh * 2 + 1];
                if (bias) { v0 += bias[gn]; v1 += bias[gn + 1]; }
                v0 *= rs; v1 *= rs;
                long off = (long)gm * ldc + gn;
                if (act == 1) { v0 = tanhf(v0); v1 = tanhf(v1); }
                else if (act == 2) {
                    v0 = 1.f / (1.f + expf(-v0));
                    v1 = 1.f / (1.f + expf(-v1));
                }
                else if (act == 3) {
                    float g0 = 1.f / (1.f + expf(-v0));
                    float g1 = 1.f / (1.f + expf(-v1));
                    v0 = g0 * e1[off]     + (1.f - g0) * e2[off];
                    v1 = g1 * e1[off + 1] + (1.f - g1) * e2[off + 1];
                }
                if (roundOut) { v0 = rna(v0); v1 = rna(v1); }
                *(float2*)(Cout + off) = make_float2(v0, v1);
                if (Ct) *(float2*)(Ct + off) = make_float2(rna(v0), rna(v1));
            }
        }
    }
}

// ---------------- fused pairwise scorer (3 j's per thread, l+dp hoisted) ----------------
__global__ void scorer_kernel(const float* __restrict__ lr,
                              const float* __restrict__ dp,
                              const float* __restrict__ Wo,
                              const float* __restrict__ bo,
                              const int* __restrict__ span_begin,
                              const int* __restrict__ span_end,
                              float* __restrict__ scores,
                              int first)
{
    int i = blockIdx.x, b = blockIdx.y;
    int tid = threadIdx.x;  // 128

    __shared__ float s_t[NB_][HP_];   // l_i + dp[bucket]
    __shared__ float s_w[L_][HP_];
    __shared__ float s_bo[L_];

    const float* lrow = lr + (long)(b * K_ + i) * LRWP_;
    for (int x = tid; x < NB_ * HP_; x += 128) {
        int n = x / HP_, h = x % HP_;
        s_t[n][h] = lrow[h] + dp[x];
    }
    for (int x = tid; x < L_ * HP_; x += 128) {
        int c = x / HP_, h = x % HP_;
        s_w[c][h] = (h < H_) ? Wo[h * L_ + c] : 0.f;
    }
    if (tid < L_) s_bo[tid] = bo[tid];
    __syncthreads();

    int endi = span_end[b * K_ + i];
    const float* rbase = lr + (long)b * K_ * LRWP_ + HP_;

    int j0 = tid, j1 = tid + 128, j2 = tid + 256;

    auto bucket = [&](int j) {
        int d = span_begin[b * K_ + j] - endi;
        int da = d < 0 ? -d : d;
        if (da <= 4) return da;
        int lg = 31 - __clz(da) + 3;
        return lg < (NB_ - 1) ? lg : (NB_ - 1);
    };
    const float* t0 = s_t[bucket(j0)];
    const float* t1 = s_t[bucket(j1)];
    const float* t2 = s_t[bucket(j2)];
    const float* r0 = rbase + (long)j0 * LRWP_;
    const float* r1 = rbase + (long)j1 * LRWP_;
    const float* r2 = rbase + (long)j2 * LRWP_;

    float acc[3][L_];
    #pragma unroll
    for (int c = 0; c < L_; c++) {
        acc[0][c] = s_bo[c]; acc[1][c] = s_bo[c]; acc[2][c] = s_bo[c];
    }

    #pragma unroll 2
    for (int h = 0; h < HP_; h += 4) {
        float4 tv0 = *(const float4*)(t0 + h);
        float4 tv1 = *(const float4*)(t1 + h);
        float4 tv2 = *(const float4*)(t2 + h);
        float4 rv0 = *(const float4*)(r0 + h);
        float4 rv1 = *(const float4*)(r1 + h);
        float4 rv2 = *(const float4*)(r2 + h);

        float h00 = fmaxf(tv0.x + rv0.x, 0.f);
        float h01 = fmaxf(tv0.y + rv0.y, 0.f);
        float h02 = fmaxf(tv0.z + rv0.z, 0.f);
        float h03 = fmaxf(tv0.w + rv0.w, 0.f);
        float h10 = fmaxf(tv1.x + rv1.x, 0.f);
        float h11 = fmaxf(tv1.y + rv1.y, 0.f);
        float h12 = fmaxf(tv1.z + rv1.z, 0.f);
        float h13 = fmaxf(tv1.w + rv1.w, 0.f);
        float h20 = fmaxf(tv2.x + rv2.x, 0.f);
        float h21 = fmaxf(tv2.y + rv2.y, 0.f);
        float h22 = fmaxf(tv2.z + rv2.z, 0.f);
        float h23 = fmaxf(tv2.w + rv2.w, 0.f);

        #pragma unroll
        for (int c = 0; c < L_; c++) {
            float4 w = *(const float4*)(&s_w[c][h]);
            acc[0][c] += h00 * w.x + h01 * w.y + h02 * w.z + h03 * w.w;
            acc[1][c] += h10 * w.x + h11 * w.y + h12 * w.z + h13 * w.w;
            acc[2][c] += h20 * w.x + h21 * w.y + h22 * w.z + h23 * w.w;
        }
    }

    long rowoff = ((long)(b * K_ + i)) * K_;
    #pragma unroll
    for (int jj = 0; jj < 3; jj++) {
        int j = tid + jj * 128;
        float* out = scores + (rowoff + j) * L_;
        if (first) {
            #pragma unroll
            for (int q = 0; q < 3; q++)
                *(float4*)(out + q * 4) = make_float4(acc[jj][q*4], acc[jj][q*4+1],
                                                      acc[jj][q*4+2], acc[jj][q*4+3]);
        } else {
            #pragma unroll
            for (int q = 0; q < 3; q++) {
                float4 old = *(const float4*)(out + q * 4);
                *(float4*)(out + q * 4) = make_float4(old.x + acc[jj][q*4], old.y + acc[jj][q*4+1],
                                                      old.z + acc[jj][q*4+2], old.w + acc[jj][q*4+3]);
            }
        }
    }
}

// ---------------- probs = sigmoid(max_l scores) * mask (tf32-clean) + transpose ----------------
__global__ void probs_kernel(const float* __restrict__ scores,
                             const float* __restrict__ mask,
                             float* __restrict__ probsAll)
{
    int i = blockIdx.x, b = blockIdx.y;
    for (int j = threadIdx.x; j < K_; j += blockDim.x) {
        const float* s = scores + (((long)(b * K_ + i)) * K_ + j) * L_;
        float m = s[0];
        #pragma unroll
        for (int c = 1; c < L_; c++) m = fmaxf(m, s[c]);
        float p = rna((1.f / (1.f + expf(-m))) * mask[((long)(b * K_ + i)) * K_ + j]);
        probsAll[((long)(b * K_ + i)) * K_ + j] = p;
        probsAll[(long)SZ_P + ((long)(b * K_ + j)) * K_ + i] = p;
    }
}

// ---------------- inverse row sums over probsAll (2*B*K rows) ----------------
__global__ void invsum_kernel(const float* __restrict__ probsAll,
                              float* __restrict__ invAll)
{
    int row = blockIdx.x;
    const float* src = probsAll + (long)row * K_;
    float s = 0.f;
    for (int j = threadIdx.x; j < K_; j += blockDim.x) s += src[j];
    __shared__ float red[4];
    #pragma unroll
    for (int o = 16; o > 0; o >>= 1) s += __shfl_down_sync(0xffffffffu, s, o);
    int wid = threadIdx.x >> 5;
    if ((threadIdx.x & 31) == 0) red[wid] = s;
    __syncthreads();
    if (threadIdx.x == 0) {
        s = red[0] + red[1] + red[2] + red[3];
        invAll[row] = 1.f / (s + 1e-7f);
    }
}

// ---------------- scatter with last-write-wins semantics ----------------
__global__ void scatter_kernel(const float* __restrict__ u,
                               const float* __restrict__ all_span,
                               const int* __restrict__ prune,
                               const int* __restrict__ span_len,
                               float* __restrict__ out_all)
{
    int bk = blockIdx.x;
    int b = bk / K_, k = bk % K_;
    int idx = prune[bk];
    bool last = (k == K_ - 1) || (prune[bk + 1] != idx);
    if (!last) return;
    bool valid = k < span_len[b];
    const float* src = valid ? (u + (long)bk * D_)
                             : (all_span + ((long)b * N_ + idx) * D_);
    float* dst = out_all + ((long)b * N_ + idx) * D_;
    int t = threadIdx.x;
    float4 v = *(const float4*)(src + t * 4);
    *(float4*)(dst + t * 4) = v;
}

// ---------------- host orchestration ----------------
extern "C" void kernel_launch(void* const* d_in, const int* in_sizes, int n_in,
                              void* d_out, int out_size)
{
    const float* span_vecs  = (const float*)d_in[0];
    const float* all_span   = (const float*)d_in[1];
    const int*   span_begin = (const int*)  d_in[2];
    const int*   span_end   = (const int*)  d_in[3];
    const float* mask       = (const float*)d_in[4];
    const int*   prune      = (const int*)  d_in[5];
    const int*   span_len   = (const int*)  d_in[6];
    const float* Wl  = (const float*)d_in[8];
    const float* bl  = (const float*)d_in[9];
    const float* Wr  = (const float*)d_in[10];
    const float* br  = (const float*)d_in[11];
    const float* de  = (const float*)d_in[12];
    const float* Wd  = (const float*)d_in[13];
    const float* bd  = (const float*)d_in[14];
    const float* Wo  = (const float*)d_in[15];
    const float* bo  = (const float*)d_in[16];
    const float* Wff1= (const float*)d_in[17];
    const float* Wff2= (const float*)d_in[18];
    const float* Wg  = (const float*)d_in[19];
    const float* bg  = (const float*)d_in[20];

    float *u, *u2, *ut, *ut2, *lr, *wlr, *blr, *dp, *probsAll, *invAll, *c, *tmp, *ctxt;
    float *wff1t, *wff2t, *wgt;
    cudaGetSymbolAddress((void**)&u,        g_u);
    cudaGetSymbolAddress((void**)&u2,       g_u2);
    cudaGetSymbolAddress((void**)&ut,       g_ut);
    cudaGetSymbolAddress((void**)&ut2,      g_ut2);
    cudaGetSymbolAddress((void**)&lr,       g_lr);
    cudaGetSymbolAddress((void**)&wlr,      g_wlr);
    cudaGetSymbolAddress((void**)&blr,      g_blr);
    cudaGetSymbolAddress((void**)&dp,       g_dp);
    cudaGetSymbolAddress((void**)&probsAll, g_probs);
    cudaGetSymbolAddress((void**)&invAll,   g_inv);
    cudaGetSymbolAddress((void**)&c,        g_c);
    cudaGetSymbolAddress((void**)&tmp,      g_tmp);
    cudaGetSymbolAddress((void**)&ctxt,     g_ctxt);
    cudaGetSymbolAddress((void**)&wff1t,    g_wff1t);
    cudaGetSymbolAddress((void**)&wff2t,    g_wff2t);
    cudaGetSymbolAddress((void**)&wgt,      g_wgt);

    float* out_all = (float*)d_out;
    float* out_u   = out_all + (size_t)B_ * N_ * D_;
    float* out_sc  = out_u   + (size_t)B_ * K_ * D_;

    const int M = B_ * K_;  // 768

    // dynamic smem sizes: 3 stages of (BM*36 + 32*72) unsigned
    const int smem64 = 3 * (64 * ASTRIDE + 32 * BSTRIDE) * 4;  // 55296
    const int smem32 = 3 * (32 * ASTRIDE + 32 * BSTRIDE) * 4;  // 41472
    cudaFuncSetAttribute(mma_gemm<64>, cudaFuncAttributeMaxDynamicSharedMemorySize, smem64);

    convert_kernel<<<148, 256>>>(Wff1, Wff2, Wg, span_vecs, wff1t, wff2t, wgt, u, ut);
    init_kernel<<<128, 256>>>(de, Wd, bd, Wl, bl, Wr, br, dp, wlr, blr);

    float *ucur = u,  *unext = u2;
    float *utcur = ut, *utnext = ut2;

    // initial l|r projection + scorer
    mma_gemm<32><<<dim3(6, 24, 1), 128, smem32>>>(utcur, utcur, utcur, wlr, blr, nullptr, nullptr, nullptr,
                                                  lr, nullptr, M, LRWP_, D_, D_, LRWP_, 0, 0, 0, 0, 0, 0, 0);
    scorer_kernel<<<dim3(K_, B_), 128>>>(lr, dp, Wo, bo, span_begin, span_end, out_sc, 1);

    for (int it = 0; it < 2; it++) {
        probs_kernel<<<dim3(K_, B_), 128>>>(out_sc, mask, probsAll);
        invsum_kernel<<<2 * B_ * K_, 128>>>(probsAll, invAll);

        // c[z] = (probsAll[z] @ ut[z&1]) * invAll[z]  (tf32-clean out)
        mma_gemm<64><<<dim3(16, 6, 4), 128, smem64>>>(probsAll, probsAll, probsAll, utcur, nullptr, invAll,
                                                      nullptr, nullptr, c, nullptr,
                                                      K_, D_, K_, K_, D_,
                                                      (long)K_*K_, (long)K_*D_, 1, (long)K_*D_, K_, 0, 1);

        // tmp = tanh([ut|c1|c2] @ Wff1)  (tf32-clean out)
        mma_gemm<64><<<dim3(16, 12, 1), 128, smem64>>>(utcur, c, c + SZ_U, wff1t, nullptr, nullptr,
                                                       nullptr, nullptr, tmp, nullptr,
                                                       M, D_, 3 * D_, D_, D_, 0, 0, 0, 0, 0, 1, 1);
        // ctxt = tmp @ Wff2  (tf32-clean out)
        mma_gemm<64><<<dim3(16, 12, 1), 128, smem64>>>(tmp, tmp, tmp, wff2t, nullptr, nullptr,
                                                       nullptr, nullptr, ctxt, nullptr,
                                                       M, D_, D_, D_, D_, 0, 0, 0, 0, 0, 0, 1);
        // unext = g*u + (1-g)*ctxt (fp32), utnext = rna(unext)
        mma_gemm<64><<<dim3(16, 12, 1), 128, smem64>>>(utcur, ctxt, ctxt, wgt, bg, nullptr,
                                                       ucur, ctxt, unext, utnext,
                                                       M, D_, 2 * D_, D_, D_, 0, 0, 0, 0, 0, 3, 0);
        float* s1 = ucur; ucur = unext; unext = s1;
        float* s2 = utcur; utcur = utnext; utnext = s2;

        // re-project + scorer (residual accumulate)
        mma_gemm<32><<<dim3(6, 24, 1), 128, smem32>>>(utcur, utcur, utcur, wlr, blr, nullptr, nullptr, nullptr,
                                                      lr, nullptr, M, LRWP_, D_, D_, LRWP_, 0, 0, 0, 0, 0, 0, 0);
        scorer_kernel<<<dim3(K_, B_), 128>>>(lr, dp, Wo, bo, span_begin, span_end, out_sc, 0);
    }

    // outputs: update_all, u, scores (scores already written in place)
    cudaMemcpyAsync(out_all, all_span, sizeof(float) * (size_t)B_ * N_ * D_, cudaMemcpyDeviceToDevice);
    scatter_kernel<<<B_ * K_, 256>>>(ucur, all_span, prune, span_len, out_all);
    cudaMemcpyAsync(out_u, ucur, sizeof(float) * SZ_U, cudaMemcpyDeviceToDevice);
}